// round 9
// baseline (speedup 1.0000x reference)
#include <cuda_runtime.h>
#include <cuda_bf16.h>
#include <math.h>
#include <stdint.h>

#define BATCH  4
#define SEQ    2048
#define DMODEL 1024
#define NHEADS 16
#define HD     64
#define NF     256
#define BH     (BATCH*NHEADS)       // 128
#define MROWS  (BATCH*SEQ)          // 8192

// ---------------- scratch (static device globals; no allocations) ------------
__device__ float g_q  [MROWS*DMODEL];   // [B,S,D]
__device__ float g_k  [MROWS*DMODEL];
__device__ float g_v  [MROWS*DMODEL];
__device__ float g_ctx[MROWS*DMODEL];
// packed bf16x2 hi/lo feature projections, [BH][SEQ][NF/2] words
__device__ uint32_t g_qph[(size_t)BH*SEQ*(NF/2)];
__device__ uint32_t g_qpl[(size_t)BH*SEQ*(NF/2)];
__device__ uint32_t g_kph[(size_t)BH*SEQ*(NF/2)];
__device__ uint32_t g_kpl[(size_t)BH*SEQ*(NF/2)];

// ---------------- helpers ----------------------------------------------------
__device__ __forceinline__ void split_pack(float x, float y, uint32_t& hi, uint32_t& lo) {
    __nv_bfloat162 h = __floats2bfloat162_rn(x, y);
    float hx = __bfloat162float(h.x);
    float hy = __bfloat162float(h.y);
    __nv_bfloat162 l = __floats2bfloat162_rn(x - hx, y - hy);
    hi = *reinterpret_cast<uint32_t*>(&h);
    lo = *reinterpret_cast<uint32_t*>(&l);
}

__device__ __forceinline__ void mma16(float* c, const uint32_t* a, const uint32_t* b) {
    asm volatile(
        "mma.sync.aligned.m16n8k16.row.col.f32.bf16.bf16.f32 "
        "{%0,%1,%2,%3}, {%4,%5,%6,%7}, {%8,%9}, {%0,%1,%2,%3};\n"
        : "+f"(c[0]), "+f"(c[1]), "+f"(c[2]), "+f"(c[3])
        : "r"(a[0]), "r"(a[1]), "r"(a[2]), "r"(a[3]), "r"(b[0]), "r"(b[1]));
}
__device__ __forceinline__ void mma3(float* c, const uint32_t* ah, const uint32_t* al,
                                     const uint32_t* bh, const uint32_t* bl) {
    mma16(c, ah, bl);
    mma16(c, al, bh);
    mma16(c, ah, bh);
}

__device__ __forceinline__ void ldsm4(uint32_t& r0, uint32_t& r1, uint32_t& r2,
                                      uint32_t& r3, uint32_t addr) {
    asm volatile("ldmatrix.sync.aligned.m8n8.x4.shared.b16 {%0,%1,%2,%3}, [%4];"
        : "=r"(r0), "=r"(r1), "=r"(r2), "=r"(r3) : "r"(addr));
}
__device__ __forceinline__ uint32_t s2u(const void* p) {
    uint32_t a;
    asm("{ .reg .u64 t; cvta.to.shared.u64 t, %1; cvt.u32.u64 %0, t; }" : "=r"(a) : "l"(p));
    return a;
}

// ---------------- bf16x3 GEMM: C[M,N] = A[M,K] @ W[N,K]^T + b ----------------
// Block tile 128x128, 8 warps (4 row-groups x 2 col-halves), warp tile 32x64.
// BK=32, register-staged prefetch of the next k-slab.
__global__ __launch_bounds__(256) void gemm_bf3(
    const float* __restrict__ A, const float* __restrict__ W,
    const float* __restrict__ bias, float* __restrict__ C,
    int N, int K)
{
    __shared__ uint32_t Ash[128 * 20], Asl[128 * 20];
    __shared__ uint32_t Wsh[128 * 20], Wsl[128 * 20];
    const int tid  = threadIdx.x;
    const int lane = tid & 31, warp = tid >> 5;
    const int g = lane >> 2, tig = lane & 3;
    const int wq = warp >> 1;            // 0..3: 32-row group
    const int wn = warp & 1;             // 0..1: 64-col half
    const int row0 = blockIdx.y * 128, col0 = blockIdx.x * 128;

    const int ar = tid >> 1, ak = (tid & 1) * 16;   // loaders: 128 rows x 32k
    const int arow = ((lane >> 3) & 1) * 8 + (lane & 7);
    const int acol = (lane >> 4) * 4;
    const int brow = (lane >> 4) * 8 + (lane & 7);
    const int bcol = ((lane >> 3) & 1) * 4;

    uint32_t aOffH[2], aOffL[2], bOffH[4], bOffL[4];
    {
        uint32_t AshU = s2u(Ash), AslU = s2u(Asl), WshU = s2u(Wsh), WslU = s2u(Wsl);
        #pragma unroll
        for (int mi = 0; mi < 2; mi++) {
            uint32_t off = ((wq * 32 + mi * 16 + arow) * 20 + acol) * 4;
            aOffH[mi] = AshU + off;
            aOffL[mi] = AslU + off;
        }
        #pragma unroll
        for (int jj = 0; jj < 4; jj++) {
            uint32_t off = ((wn * 64 + jj * 16 + brow) * 20 + bcol) * 4;
            bOffH[jj] = WshU + off;
            bOffL[jj] = WslU + off;
        }
    }

    float c[2][8][4] = {};
    float aS[16], wS[16];

    // preload slab 0
    {
        const float* sa = A + (size_t)(row0 + ar) * K + ak;
        const float* sw = W + (size_t)(col0 + ar) * K + ak;
        #pragma unroll
        for (int i = 0; i < 4; i++) {
            *(float4*)&aS[i * 4] = *(const float4*)(sa + i * 4);
            *(float4*)&wS[i * 4] = *(const float4*)(sw + i * 4);
        }
    }

    for (int k0 = 0; k0 < K; k0 += 32) {
        if (k0) __syncthreads();
        {
            int w = ar * 20 + (ak >> 1);
            #pragma unroll
            for (int i = 0; i < 8; i++)
                split_pack(aS[2 * i], aS[2 * i + 1], Ash[w + i], Asl[w + i]);
            #pragma unroll
            for (int i = 0; i < 8; i++)
                split_pack(wS[2 * i], wS[2 * i + 1], Wsh[w + i], Wsl[w + i]);
        }
        __syncthreads();
        if (k0 + 32 < K) {
            const float* sa = A + (size_t)(row0 + ar) * K + k0 + 32 + ak;
            const float* sw = W + (size_t)(col0 + ar) * K + k0 + 32 + ak;
            #pragma unroll
            for (int i = 0; i < 4; i++) {
                *(float4*)&aS[i * 4] = *(const float4*)(sa + i * 4);
                *(float4*)&wS[i * 4] = *(const float4*)(sw + i * 4);
            }
        }
        #pragma unroll
        for (int ks = 0; ks < 2; ks++) {
            uint32_t wbb = ks * 32;
            uint32_t ah[2][4], al[2][4], bh[8][2], bl[8][2];
            #pragma unroll
            for (int mi = 0; mi < 2; mi++) {
                ldsm4(ah[mi][0], ah[mi][1], ah[mi][2], ah[mi][3], aOffH[mi] + wbb);
                ldsm4(al[mi][0], al[mi][1], al[mi][2], al[mi][3], aOffL[mi] + wbb);
            }
            #pragma unroll
            for (int jj = 0; jj < 4; jj++) {
                ldsm4(bh[jj*2][0], bh[jj*2][1], bh[jj*2+1][0], bh[jj*2+1][1], bOffH[jj] + wbb);
                ldsm4(bl[jj*2][0], bl[jj*2][1], bl[jj*2+1][0], bl[jj*2+1][1], bOffL[jj] + wbb);
            }
            #pragma unroll
            for (int mi = 0; mi < 2; mi++)
                #pragma unroll
                for (int n = 0; n < 8; n++)
                    mma3(c[mi][n], ah[mi], al[mi], bh[n], bl[n]);
        }
    }
    #pragma unroll
    for (int mi = 0; mi < 2; mi++) {
        #pragma unroll
        for (int n = 0; n < 8; n++) {
            int col = col0 + wn * 64 + n * 8 + 2 * tig;
            float b0 = bias[col], b1 = bias[col + 1];
            int r0 = row0 + wq * 32 + mi * 16 + g;
            *(float2*)&C[(size_t)r0 * N + col] =
                make_float2(c[mi][n][0] + b0, c[mi][n][1] + b1);
            *(float2*)&C[(size_t)(r0 + 8) * N + col] =
                make_float2(c[mi][n][2] + b0, c[mi][n][3] + b1);
        }
    }
}

// ---------------- feature projection (bf16x3 MMA) ----------------------------
// Out[bh][s][f] = sum_d In[b,s,h*64+d] * P[f,d]; K=64 single slab, pitch 36.
// Block 128 rows x 128 f-cols; epilogue splits C frags straight to hi/lo words.
#define FPITCH 36
__global__ __launch_bounds__(256) void featproj_mma(
    const float* __restrict__ In, const float* __restrict__ P,
    uint32_t* __restrict__ Oh, uint32_t* __restrict__ Ol)
{
    extern __shared__ uint32_t fsm[];
    uint32_t* Ash = fsm;                    // 128*36
    uint32_t* Asl = Ash + 128 * FPITCH;
    uint32_t* Wsh = Asl + 128 * FPITCH;
    uint32_t* Wsl = Wsh + 128 * FPITCH;

    const int tid  = threadIdx.x;
    const int lane = tid & 31, warp = tid >> 5;
    const int g = lane >> 2, tig = lane & 3;
    const int wq = warp >> 1, wn = warp & 1;
    const int h = blockIdx.z;
    const int row0 = blockIdx.y * 128, col0 = blockIdx.x * 128;

    const int ar = tid >> 1, ak = (tid & 1) * 32;

    // A fill: q rows (b,s), 64 features of head h
    {
        const float* src = In + (size_t)(row0 + ar) * DMODEL + h * HD + ak;
        int w = ar * FPITCH + (ak >> 1);
        #pragma unroll
        for (int i = 0; i < 8; i++) {
            float4 v = *(const float4*)(src + i * 4);
            split_pack(v.x, v.y, Ash[w + 2 * i], Asl[w + 2 * i]);
            split_pack(v.z, v.w, Ash[w + 2 * i + 1], Asl[w + 2 * i + 1]);
        }
    }
    // W fill: P[f, d]
    {
        const float* src = P + (size_t)(col0 + ar) * HD + ak;
        int w = ar * FPITCH + (ak >> 1);
        #pragma unroll
        for (int i = 0; i < 8; i++) {
            float4 v = *(const float4*)(src + i * 4);
            split_pack(v.x, v.y, Wsh[w + 2 * i], Wsl[w + 2 * i]);
            split_pack(v.z, v.w, Wsh[w + 2 * i + 1], Wsl[w + 2 * i + 1]);
        }
    }
    __syncthreads();

    const int arow = ((lane >> 3) & 1) * 8 + (lane & 7);
    const int acol = (lane >> 4) * 4;
    const int brow = (lane >> 4) * 8 + (lane & 7);
    const int bcol = ((lane >> 3) & 1) * 4;

    float c[2][8][4] = {};
    #pragma unroll
    for (int ks = 0; ks < 4; ks++) {
        uint32_t wbb = ks * 32;
        uint32_t ah[2][4], al[2][4], bh[8][2], bl[8][2];
        #pragma unroll
        for (int mi = 0; mi < 2; mi++) {
            uint32_t off = ((wq * 32 + mi * 16 + arow) * FPITCH + acol) * 4 + wbb;
            ldsm4(ah[mi][0], ah[mi][1], ah[mi][2], ah[mi][3], s2u(Ash) + off);
            ldsm4(al[mi][0], al[mi][1], al[mi][2], al[mi][3], s2u(Asl) + off);
        }
        #pragma unroll
        for (int jj = 0; jj < 4; jj++) {
            uint32_t off = ((wn * 64 + jj * 16 + brow) * FPITCH + bcol) * 4 + wbb;
            ldsm4(bh[jj*2][0], bh[jj*2][1], bh[jj*2+1][0], bh[jj*2+1][1], s2u(Wsh) + off);
            ldsm4(bl[jj*2][0], bl[jj*2][1], bl[jj*2+1][0], bl[jj*2+1][1], s2u(Wsl) + off);
        }
        #pragma unroll
        for (int mi = 0; mi < 2; mi++)
            #pragma unroll
            for (int n = 0; n < 8; n++)
                mma3(c[mi][n], ah[mi], al[mi], bh[n], bl[n]);
    }

    // epilogue: split to packed hi/lo [bh][s][NF/2]
    #pragma unroll
    for (int mi = 0; mi < 2; mi++) {
        #pragma unroll
        for (int n = 0; n < 8; n++) {
            int col = col0 + wn * 64 + n * 8 + 2 * tig;
            int m0 = row0 + wq * 32 + mi * 16 + g;
            int b0 = m0 >> 11, s0 = m0 & 2047;
            size_t base0 = ((size_t)(b0 * NHEADS + h) * SEQ + s0) * (NF / 2) + (col >> 1);
            split_pack(c[mi][n][0], c[mi][n][1], Oh[base0], Ol[base0]);
            int m1 = m0 + 8;
            int b1 = m1 >> 11, s1 = m1 & 2047;
            size_t base1 = ((size_t)(b1 * NHEADS + h) * SEQ + s1) * (NF / 2) + (col >> 1);
            split_pack(c[mi][n][2], c[mi][n][3], Oh[base1], Ol[base1]);
        }
    }
}

// ---------------- flash attention: Q in regs, P in regs, 2 CTA/SM ------------
#define QT 64
#define TT 64
#define KW 132        // K tile pitch (words): NF/2 + 4
#define VTW 36        // V^T pitch (words): TT/2 + 4

__global__ __launch_bounds__(128) void attn_bf3(
    const uint32_t* __restrict__ Qh, const uint32_t* __restrict__ Ql,
    const uint32_t* __restrict__ Kh, const uint32_t* __restrict__ Kl,
    const float* __restrict__ V, float* __restrict__ Ctx)
{
    extern __shared__ uint32_t smw[];
    uint32_t* Ksh = smw;                    // 64*132
    uint32_t* Ksl = Ksh + QT * KW;
    uint32_t* VtH = Ksl + QT * KW;          // 64*36
    uint32_t* VtL = VtH + 64 * VTW;

    const int tid  = threadIdx.x;
    const int lane = tid & 31, warp = tid >> 5;       // warp 0..3
    const int g = lane >> 2, tig = lane & 3;
    const int bh = blockIdx.y, b = bh >> 4, h = bh & 15;
    const int s0 = blockIdx.x * QT;
    const float scale = 0.0625f;   // 1/sqrt(256)

    const int arow = ((lane >> 3) & 1) * 8 + (lane & 7);
    const int acol = (lane >> 4) * 4;
    const int brow = (lane >> 4) * 8 + (lane & 7);
    const int bcol = ((lane >> 3) & 1) * 4;

    // ---- stage Q tile into K buffers, then load A-frags to registers ----
    for (int idx = tid; idx < QT * 32; idx += 128) {
        int r = idx >> 5, w4 = (idx & 31) << 2;
        size_t gb = ((size_t)bh * SEQ + s0 + r) * (NF / 2) + w4;
        *(uint4*)&Ksh[r * KW + w4] = *(const uint4*)&Qh[gb];
        *(uint4*)&Ksl[r * KW + w4] = *(const uint4*)&Ql[gb];
    }
    __syncthreads();
    uint32_t qfh[16][4], qfl[16][4];
    {
        uint32_t baseH = s2u(Ksh) + ((warp * 16 + arow) * KW + acol) * 4;
        uint32_t baseL = s2u(Ksl) + ((warp * 16 + arow) * KW + acol) * 4;
        #pragma unroll
        for (int ks = 0; ks < 16; ks++) {
            ldsm4(qfh[ks][0], qfh[ks][1], qfh[ks][2], qfh[ks][3], baseH + ks * 32);
            ldsm4(qfl[ks][0], qfl[ks][1], qfl[ks][2], qfl[ks][3], baseL + ks * 32);
        }
    }

    const uint32_t kBh = s2u(Ksh) + (brow * KW + bcol) * 4;
    const uint32_t kBl = s2u(Ksl) + (brow * KW + bcol) * 4;
    const uint32_t vBh = s2u(VtH) + (brow * VTW + bcol) * 4;
    const uint32_t vBl = s2u(VtL) + (brow * VTW + bcol) * 4;

    float o[8][4] = {};
    float m0 = -1e30f, m1 = -1e30f, l0 = 0.f, l1 = 0.f;

    for (int t0 = 0; t0 < SEQ; t0 += TT) {
        __syncthreads();
        for (int idx = tid; idx < TT * 32; idx += 128) {
            int r = idx >> 5, w4 = (idx & 31) << 2;
            size_t gb = ((size_t)bh * SEQ + t0 + r) * (NF / 2) + w4;
            *(uint4*)&Ksh[r * KW + w4] = *(const uint4*)&Kh[gb];
            *(uint4*)&Ksl[r * KW + w4] = *(const uint4*)&Kl[gb];
        }
        for (int idx = tid; idx < TT * 16; idx += 128) {
            int t = idx >> 4, d4 = (idx & 15) << 2;
            float4 v = *(const float4*)&V[((size_t)b * SEQ + t0 + t) * DMODEL + h * HD + d4];
            float4 p;
            p.x = __shfl_xor_sync(0xffffffffu, v.x, 16);
            p.y = __shfl_xor_sync(0xffffffffu, v.y, 16);
            p.z = __shfl_xor_sync(0xffffffffu, v.z, 16);
            p.w = __shfl_xor_sync(0xffffffffu, v.w, 16);
            float ve[4], vo[4];
            if (t & 1) {
                ve[0]=p.x; ve[1]=p.y; ve[2]=p.z; ve[3]=p.w;
                vo[0]=v.x; vo[1]=v.y; vo[2]=v.z; vo[3]=v.w;
            } else {
                ve[0]=v.x; ve[1]=v.y; ve[2]=v.z; ve[3]=v.w;
                vo[0]=p.x; vo[1]=p.y; vo[2]=p.z; vo[3]=p.w;
            }
            int i0 = (t & 1) ? 2 : 0;
            int tw = t >> 1;
            #pragma unroll
            for (int i = 0; i < 2; i++) {
                uint32_t hw, lw;
                split_pack(ve[i0 + i], vo[i0 + i], hw, lw);
                VtH[(d4 + i0 + i) * VTW + tw] = hw;
                VtL[(d4 + i0 + i) * VTW + tw] = lw;
            }
        }
        __syncthreads();

        float c[8][4] = {};
        #pragma unroll
        for (int ks = 0; ks < 16; ks++) {
            uint32_t wbb = ks * 32;
            uint32_t bhf[8][2], blf[8][2];
            #pragma unroll
            for (int jj = 0; jj < 4; jj++) {
                uint32_t joff = jj * 16 * KW * 4 + wbb;
                ldsm4(bhf[jj*2][0], bhf[jj*2][1], bhf[jj*2+1][0], bhf[jj*2+1][1], kBh + joff);
                ldsm4(blf[jj*2][0], blf[jj*2][1], blf[jj*2+1][0], blf[jj*2+1][1], kBl + joff);
            }
            #pragma unroll
            for (int n = 0; n < 8; n++)
                mma3(c[n], qfh[ks], qfl[ks], bhf[n], blf[n]);
        }

        float mx0 = -1e30f, mx1 = -1e30f;
        #pragma unroll
        for (int n = 0; n < 8; n++) {
            mx0 = fmaxf(mx0, fmaxf(c[n][0], c[n][1]));
            mx1 = fmaxf(mx1, fmaxf(c[n][2], c[n][3]));
        }
        mx0 = fmaxf(mx0, __shfl_xor_sync(0xffffffffu, mx0, 1));
        mx0 = fmaxf(mx0, __shfl_xor_sync(0xffffffffu, mx0, 2));
        mx1 = fmaxf(mx1, __shfl_xor_sync(0xffffffffu, mx1, 1));
        mx1 = fmaxf(mx1, __shfl_xor_sync(0xffffffffu, mx1, 2));
        float mn0 = fmaxf(m0, mx0 * scale), mn1 = fmaxf(m1, mx1 * scale);
        float a0 = __expf(m0 - mn0), a1 = __expf(m1 - mn1);
        float sum0 = 0.f, sum1 = 0.f;
        #pragma unroll
        for (int n = 0; n < 8; n++) {
            c[n][0] = __expf(fmaf(c[n][0], scale, -mn0));
            c[n][1] = __expf(fmaf(c[n][1], scale, -mn0));
            c[n][2] = __expf(fmaf(c[n][2], scale, -mn1));
            c[n][3] = __expf(fmaf(c[n][3], scale, -mn1));
            sum0 += c[n][0] + c[n][1];
            sum1 += c[n][2] + c[n][3];
        }
        sum0 += __shfl_xor_sync(0xffffffffu, sum0, 1);
        sum0 += __shfl_xor_sync(0xffffffffu, sum0, 2);
        sum1 += __shfl_xor_sync(0xffffffffu, sum1, 1);
        sum1 += __shfl_xor_sync(0xffffffffu, sum1, 2);
        l0 = l0 * a0 + sum0; m0 = mn0;
        l1 = l1 * a1 + sum1; m1 = mn1;

        uint32_t pfh[4][4], pfl[4][4];
        #pragma unroll
        for (int k2 = 0; k2 < 4; k2++) {
            split_pack(c[2*k2  ][0], c[2*k2  ][1], pfh[k2][0], pfl[k2][0]);
            split_pack(c[2*k2  ][2], c[2*k2  ][3], pfh[k2][1], pfl[k2][1]);
            split_pack(c[2*k2+1][0], c[2*k2+1][1], pfh[k2][2], pfl[k2][2]);
            split_pack(c[2*k2+1][2], c[2*k2+1][3], pfh[k2][3], pfl[k2][3]);
        }

        #pragma unroll
        for (int n = 0; n < 8; n++) {
            o[n][0] *= a0; o[n][1] *= a0;
            o[n][2] *= a1; o[n][3] *= a1;
        }
        #pragma unroll
        for (int k2 = 0; k2 < 4; k2++) {
            uint32_t wbb = k2 * 32;
            uint32_t bhf[8][2], blf[8][2];
            #pragma unroll
            for (int jj = 0; jj < 4; jj++) {
                uint32_t joff = jj * 16 * VTW * 4 + wbb;
                ldsm4(bhf[jj*2][0], bhf[jj*2][1], bhf[jj*2+1][0], bhf[jj*2+1][1], vBh + joff);
                ldsm4(blf[jj*2][0], blf[jj*2][1], blf[jj*2+1][0], blf[jj*2+1][1], vBl + joff);
            }
            #pragma unroll
            for (int n = 0; n < 8; n++)
                mma3(o[n], pfh[k2], pfl[k2], bhf[n], blf[n]);
        }
    }

    float inv0 = 1.0f / l0, inv1 = 1.0f / l1;
    int r0 = s0 + warp * 16 + g;
    #pragma unroll
    for (int n = 0; n < 8; n++) {
        int dc = n * 8 + 2 * tig;
        *(float2*)&Ctx[((size_t)b * SEQ + r0) * DMODEL + h * HD + dc] =
            make_float2(o[n][0] * inv0, o[n][1] * inv0);
        *(float2*)&Ctx[((size_t)b * SEQ + r0 + 8) * DMODEL + h * HD + dc] =
            make_float2(o[n][2] * inv1, o[n][3] * inv1);
    }
}

// ---------------- launch ------------------------------------------------------
extern "C" void kernel_launch(void* const* d_in, const int* in_sizes, int n_in,
                              void* d_out, int out_size)
{
    (void)in_sizes; (void)n_in; (void)out_size;
    const float* x  = (const float*)d_in[0];
    const float* Wq = (const float*)d_in[1];
    const float* bq = (const float*)d_in[2];
    const float* Wk = (const float*)d_in[3];
    const float* bk = (const float*)d_in[4];
    const float* Wv = (const float*)d_in[5];
    const float* bv = (const float*)d_in[6];
    const float* Wo = (const float*)d_in[7];
    const float* bo = (const float*)d_in[8];
    const float* P  = (const float*)d_in[9];

    float *q, *k, *v, *ctx;
    uint32_t *qph, *qpl, *kph, *kpl;
    cudaGetSymbolAddress((void**)&q,   g_q);
    cudaGetSymbolAddress((void**)&k,   g_k);
    cudaGetSymbolAddress((void**)&v,   g_v);
    cudaGetSymbolAddress((void**)&ctx, g_ctx);
    cudaGetSymbolAddress((void**)&qph, g_qph);
    cudaGetSymbolAddress((void**)&qpl, g_qpl);
    cudaGetSymbolAddress((void**)&kph, g_kph);
    cudaGetSymbolAddress((void**)&kpl, g_kpl);

    dim3 gemm_grid(DMODEL / 128, MROWS / 128);   // (8, 64)
    gemm_bf3<<<gemm_grid, 256>>>(x, Wq, bq, q, DMODEL, DMODEL);
    gemm_bf3<<<gemm_grid, 256>>>(x, Wk, bk, k, DMODEL, DMODEL);
    gemm_bf3<<<gemm_grid, 256>>>(x, Wv, bv, v, DMODEL, DMODEL);

    const int FP_SMEM = 4 * 128 * FPITCH * 4;    // 73728 B
    cudaFuncSetAttribute(featproj_mma, cudaFuncAttributeMaxDynamicSharedMemorySize, FP_SMEM);
    dim3 fp_grid(NF / 128, MROWS / 128, NHEADS); // (2, 64, 16)
    featproj_mma<<<fp_grid, 256, FP_SMEM>>>(q, P, qph, qpl);
    featproj_mma<<<fp_grid, 256, FP_SMEM>>>(k, P, kph, kpl);

    const int ATT_SMEM = (QT * KW * 2 + 64 * VTW * 2) * 4;   // 86016 B -> 2 CTA/SM
    cudaFuncSetAttribute(attn_bf3, cudaFuncAttributeMaxDynamicSharedMemorySize, ATT_SMEM);
    attn_bf3<<<dim3(SEQ / QT, BH), 128, ATT_SMEM>>>(qph, qpl, kph, kpl, v, ctx);

    gemm_bf3<<<gemm_grid, 256>>>(ctx, Wo, bo, (float*)d_out, DMODEL, DMODEL);
}

// round 12
// speedup vs baseline: 1.0587x; 1.0587x over previous
#include <cuda_runtime.h>
#include <cuda_bf16.h>
#include <math.h>
#include <stdint.h>

#define BATCH  4
#define SEQ    2048
#define DMODEL 1024
#define NHEADS 16
#define HD     64
#define NF     256
#define BH     (BATCH*NHEADS)       // 128
#define MROWS  (BATCH*SEQ)          // 8192

// ---------------- scratch (static device globals; no allocations) ------------
__device__ float g_q  [MROWS*DMODEL];   // [B,S,D]
__device__ float g_k  [MROWS*DMODEL];
__device__ float g_v  [MROWS*DMODEL];
__device__ float g_ctx[MROWS*DMODEL];
// packed bf16x2 hi/lo feature projections, [BH][SEQ][NF/2] words
__device__ uint32_t g_qph[(size_t)BH*SEQ*(NF/2)];
__device__ uint32_t g_qpl[(size_t)BH*SEQ*(NF/2)];
__device__ uint32_t g_kph[(size_t)BH*SEQ*(NF/2)];
__device__ uint32_t g_kpl[(size_t)BH*SEQ*(NF/2)];

// ---------------- helpers ----------------------------------------------------
__device__ __forceinline__ void split_pack(float x, float y, uint32_t& hi, uint32_t& lo) {
    __nv_bfloat162 h = __floats2bfloat162_rn(x, y);
    float hx = __bfloat162float(h.x);
    float hy = __bfloat162float(h.y);
    __nv_bfloat162 l = __floats2bfloat162_rn(x - hx, y - hy);
    hi = *reinterpret_cast<uint32_t*>(&h);
    lo = *reinterpret_cast<uint32_t*>(&l);
}

__device__ __forceinline__ void mma16(float* c, const uint32_t* a, const uint32_t* b) {
    asm volatile(
        "mma.sync.aligned.m16n8k16.row.col.f32.bf16.bf16.f32 "
        "{%0,%1,%2,%3}, {%4,%5,%6,%7}, {%8,%9}, {%0,%1,%2,%3};\n"
        : "+f"(c[0]), "+f"(c[1]), "+f"(c[2]), "+f"(c[3])
        : "r"(a[0]), "r"(a[1]), "r"(a[2]), "r"(a[3]), "r"(b[0]), "r"(b[1]));
}
__device__ __forceinline__ void mma3(float* c, const uint32_t* ah, const uint32_t* al,
                                     const uint32_t* bh, const uint32_t* bl) {
    mma16(c, ah, bl);
    mma16(c, al, bh);
    mma16(c, ah, bh);
}

__device__ __forceinline__ void ldsm4(uint32_t& r0, uint32_t& r1, uint32_t& r2,
                                      uint32_t& r3, uint32_t addr) {
    asm volatile("ldmatrix.sync.aligned.m8n8.x4.shared.b16 {%0,%1,%2,%3}, [%4];"
        : "=r"(r0), "=r"(r1), "=r"(r2), "=r"(r3) : "r"(addr));
}
__device__ __forceinline__ uint32_t s2u(const void* p) {
    uint32_t a;
    asm("{ .reg .u64 t; cvta.to.shared.u64 t, %1; cvt.u32.u64 %0, t; }" : "=r"(a) : "l"(p));
    return a;
}

// ---------------- bf16x3 GEMM (round-8 known-good: 128x64, BK=32) ------------
__global__ __launch_bounds__(256) void gemm_bf3(
    const float* __restrict__ A, const float* __restrict__ W,
    const float* __restrict__ bias, float* __restrict__ C,
    int N, int K)
{
    __shared__ uint32_t Ash[128 * 20], Asl[128 * 20];
    __shared__ uint32_t Wsh[64 * 20],  Wsl[64 * 20];
    const int tid  = threadIdx.x;
    const int lane = tid & 31, warp = tid >> 5;
    const int g = lane >> 2, tig = lane & 3;
    const int wq = warp >> 1, wn = warp & 1;
    const int row0 = blockIdx.y * 128, col0 = blockIdx.x * 64;

    const int ar = tid >> 1, ak = (tid & 1) * 16;
    const int wr = tid >> 2, wk = (tid & 3) * 8;

    const int arow = ((lane >> 3) & 1) * 8 + (lane & 7);
    const int acol = (lane >> 4) * 4;
    const int brow = (lane >> 4) * 8 + (lane & 7);
    const int bcol = ((lane >> 3) & 1) * 4;
    uint32_t aOffH[2], aOffL[2], bOffH[2], bOffL[2];
    {
        uint32_t AshU = s2u(Ash), AslU = s2u(Asl), WshU = s2u(Wsh), WslU = s2u(Wsl);
        #pragma unroll
        for (int mi = 0; mi < 2; mi++) {
            uint32_t off = ((wq * 32 + mi * 16 + arow) * 20 + acol) * 4;
            aOffH[mi] = AshU + off;
            aOffL[mi] = AslU + off;
        }
        #pragma unroll
        for (int jj = 0; jj < 2; jj++) {
            uint32_t off = ((wn * 32 + jj * 16 + brow) * 20 + bcol) * 4;
            bOffH[jj] = WshU + off;
            bOffL[jj] = WslU + off;
        }
    }

    float c[2][4][4] = {};

    for (int k0 = 0; k0 < K; k0 += 32) {
        __syncthreads();
        {
            const float* src = A + (size_t)(row0 + ar) * K + k0 + ak;
            float4 v0 = *(const float4*)(src);
            float4 v1 = *(const float4*)(src + 4);
            float4 v2 = *(const float4*)(src + 8);
            float4 v3 = *(const float4*)(src + 12);
            int w = ar * 20 + (ak >> 1);
            split_pack(v0.x, v0.y, Ash[w+0], Asl[w+0]);
            split_pack(v0.z, v0.w, Ash[w+1], Asl[w+1]);
            split_pack(v1.x, v1.y, Ash[w+2], Asl[w+2]);
            split_pack(v1.z, v1.w, Ash[w+3], Asl[w+3]);
            split_pack(v2.x, v2.y, Ash[w+4], Asl[w+4]);
            split_pack(v2.z, v2.w, Ash[w+5], Asl[w+5]);
            split_pack(v3.x, v3.y, Ash[w+6], Asl[w+6]);
            split_pack(v3.z, v3.w, Ash[w+7], Asl[w+7]);
        }
        {
            const float* src = W + (size_t)(col0 + wr) * K + k0 + wk;
            float4 v0 = *(const float4*)(src);
            float4 v1 = *(const float4*)(src + 4);
            int w = wr * 20 + (wk >> 1);
            split_pack(v0.x, v0.y, Wsh[w+0], Wsl[w+0]);
            split_pack(v0.z, v0.w, Wsh[w+1], Wsl[w+1]);
            split_pack(v1.x, v1.y, Wsh[w+2], Wsl[w+2]);
            split_pack(v1.z, v1.w, Wsh[w+3], Wsl[w+3]);
        }
        __syncthreads();
        #pragma unroll
        for (int ks = 0; ks < 2; ks++) {
            uint32_t wbb = ks * 32;
            uint32_t ah[2][4], al[2][4], bh[4][2], bl[4][2];
            #pragma unroll
            for (int mi = 0; mi < 2; mi++) {
                ldsm4(ah[mi][0], ah[mi][1], ah[mi][2], ah[mi][3], aOffH[mi] + wbb);
                ldsm4(al[mi][0], al[mi][1], al[mi][2], al[mi][3], aOffL[mi] + wbb);
            }
            #pragma unroll
            for (int jj = 0; jj < 2; jj++) {
                ldsm4(bh[jj*2][0], bh[jj*2][1], bh[jj*2+1][0], bh[jj*2+1][1], bOffH[jj] + wbb);
                ldsm4(bl[jj*2][0], bl[jj*2][1], bl[jj*2+1][0], bl[jj*2+1][1], bOffL[jj] + wbb);
            }
            #pragma unroll
            for (int mi = 0; mi < 2; mi++)
                #pragma unroll
                for (int n = 0; n < 4; n++)
                    mma3(c[mi][n], ah[mi], al[mi], bh[n], bl[n]);
        }
    }
    #pragma unroll
    for (int mi = 0; mi < 2; mi++) {
        #pragma unroll
        for (int n = 0; n < 4; n++) {
            int col = col0 + wn * 32 + n * 8 + 2 * tig;
            float b0 = bias[col], b1 = bias[col + 1];
            int r0 = row0 + wq * 32 + mi * 16 + g;
            *(float2*)&C[(size_t)r0 * N + col] =
                make_float2(c[mi][n][0] + b0, c[mi][n][1] + b1);
            *(float2*)&C[(size_t)(r0 + 8) * N + col] =
                make_float2(c[mi][n][2] + b0, c[mi][n][3] + b1);
        }
    }
}

// ---------------- feature projection (bf16x3 MMA; round-9 measured win) ------
#define FPITCH 36
__global__ __launch_bounds__(256) void featproj_mma(
    const float* __restrict__ In, const float* __restrict__ P,
    uint32_t* __restrict__ Oh, uint32_t* __restrict__ Ol)
{
    extern __shared__ uint32_t fsm[];
    uint32_t* Ash = fsm;                    // 128*36
    uint32_t* Asl = Ash + 128 * FPITCH;
    uint32_t* Wsh = Asl + 128 * FPITCH;
    uint32_t* Wsl = Wsh + 128 * FPITCH;

    const int tid  = threadIdx.x;
    const int lane = tid & 31, warp = tid >> 5;
    const int g = lane >> 2, tig = lane & 3;
    const int wq = warp >> 1, wn = warp & 1;
    const int h = blockIdx.z;
    const int row0 = blockIdx.y * 128, col0 = blockIdx.x * 128;

    const int ar = tid >> 1, ak = (tid & 1) * 32;

    {
        const float* src = In + (size_t)(row0 + ar) * DMODEL + h * HD + ak;
        int w = ar * FPITCH + (ak >> 1);
        #pragma unroll
        for (int i = 0; i < 8; i++) {
            float4 v = *(const float4*)(src + i * 4);
            split_pack(v.x, v.y, Ash[w + 2 * i], Asl[w + 2 * i]);
            split_pack(v.z, v.w, Ash[w + 2 * i + 1], Asl[w + 2 * i + 1]);
        }
    }
    {
        const float* src = P + (size_t)(col0 + ar) * HD + ak;
        int w = ar * FPITCH + (ak >> 1);
        #pragma unroll
        for (int i = 0; i < 8; i++) {
            float4 v = *(const float4*)(src + i * 4);
            split_pack(v.x, v.y, Wsh[w + 2 * i], Wsl[w + 2 * i]);
            split_pack(v.z, v.w, Wsh[w + 2 * i + 1], Wsl[w + 2 * i + 1]);
        }
    }
    __syncthreads();

    const int arow = ((lane >> 3) & 1) * 8 + (lane & 7);
    const int acol = (lane >> 4) * 4;
    const int brow = (lane >> 4) * 8 + (lane & 7);
    const int bcol = ((lane >> 3) & 1) * 4;

    float c[2][8][4] = {};
    #pragma unroll
    for (int ks = 0; ks < 4; ks++) {
        uint32_t wbb = ks * 32;
        uint32_t ah[2][4], al[2][4], bh[8][2], bl[8][2];
        #pragma unroll
        for (int mi = 0; mi < 2; mi++) {
            uint32_t off = ((wq * 32 + mi * 16 + arow) * FPITCH + acol) * 4 + wbb;
            ldsm4(ah[mi][0], ah[mi][1], ah[mi][2], ah[mi][3], s2u(Ash) + off);
            ldsm4(al[mi][0], al[mi][1], al[mi][2], al[mi][3], s2u(Asl) + off);
        }
        #pragma unroll
        for (int jj = 0; jj < 4; jj++) {
            uint32_t off = ((wn * 64 + jj * 16 + brow) * FPITCH + bcol) * 4 + wbb;
            ldsm4(bh[jj*2][0], bh[jj*2][1], bh[jj*2+1][0], bh[jj*2+1][1], s2u(Wsh) + off);
            ldsm4(bl[jj*2][0], bl[jj*2][1], bl[jj*2+1][0], bl[jj*2+1][1], s2u(Wsl) + off);
        }
        #pragma unroll
        for (int mi = 0; mi < 2; mi++)
            #pragma unroll
            for (int n = 0; n < 8; n++)
                mma3(c[mi][n], ah[mi], al[mi], bh[n], bl[n]);
    }

    #pragma unroll
    for (int mi = 0; mi < 2; mi++) {
        #pragma unroll
        for (int n = 0; n < 8; n++) {
            int col = col0 + wn * 64 + n * 8 + 2 * tig;
            int m0 = row0 + wq * 32 + mi * 16 + g;
            int b0 = m0 >> 11, s0 = m0 & 2047;
            size_t base0 = ((size_t)(b0 * NHEADS + h) * SEQ + s0) * (NF / 2) + (col >> 1);
            split_pack(c[mi][n][0], c[mi][n][1], Oh[base0], Ol[base0]);
            int m1 = m0 + 8;
            int b1 = m1 >> 11, s1 = m1 & 2047;
            size_t base1 = ((size_t)(b1 * NHEADS + h) * SEQ + s1) * (NF / 2) + (col >> 1);
            split_pack(c[mi][n][2], c[mi][n][3], Oh[base1], Ol[base1]);
        }
    }
}

// ---------------- flash attention: Q in regs, P in regs, 2 CTA/SM ------------
#define QT 64
#define TT 64
#define KW 132        // K tile pitch (words): NF/2 + 4
#define VTW 36        // V^T pitch (words): TT/2 + 4

__global__ __launch_bounds__(128) void attn_bf3(
    const uint32_t* __restrict__ Qh, const uint32_t* __restrict__ Ql,
    const uint32_t* __restrict__ Kh, const uint32_t* __restrict__ Kl,
    const float* __restrict__ V, float* __restrict__ Ctx)
{
    extern __shared__ uint32_t smw[];
    uint32_t* Ksh = smw;                    // 64*132
    uint32_t* Ksl = Ksh + QT * KW;
    uint32_t* VtH = Ksl + QT * KW;          // 64*36
    uint32_t* VtL = VtH + 64 * VTW;

    const int tid  = threadIdx.x;
    const int lane = tid & 31, warp = tid >> 5;       // warp 0..3
    const int g = lane >> 2, tig = lane & 3;
    const int bh = blockIdx.y, b = bh >> 4, h = bh & 15;
    const int s0 = blockIdx.x * QT;
    const float scale = 0.0625f;   // 1/sqrt(256)

    const int arow = ((lane >> 3) & 1) * 8 + (lane & 7);
    const int acol = (lane >> 4) * 4;
    const int brow = (lane >> 4) * 8 + (lane & 7);
    const int bcol = ((lane >> 3) & 1) * 4;

    // ---- stage Q tile into K buffers, then load A-frags to registers ----
    for (int idx = tid; idx < QT * 32; idx += 128) {
        int r = idx >> 5, w4 = (idx & 31) << 2;
        size_t gb = ((size_t)bh * SEQ + s0 + r) * (NF / 2) + w4;
        *(uint4*)&Ksh[r * KW + w4] = *(const uint4*)&Qh[gb];
        *(uint4*)&Ksl[r * KW + w4] = *(const uint4*)&Ql[gb];
    }
    __syncthreads();
    uint32_t qfh[16][4], qfl[16][4];
    {
        uint32_t baseH = s2u(Ksh) + ((warp * 16 + arow) * KW + acol) * 4;
        uint32_t baseL = s2u(Ksl) + ((warp * 16 + arow) * KW + acol) * 4;
        #pragma unroll
        for (int ks = 0; ks < 16; ks++) {
            ldsm4(qfh[ks][0], qfh[ks][1], qfh[ks][2], qfh[ks][3], baseH + ks * 32);
            ldsm4(qfl[ks][0], qfl[ks][1], qfl[ks][2], qfl[ks][3], baseL + ks * 32);
        }
    }

    const uint32_t kBh = s2u(Ksh) + (brow * KW + bcol) * 4;
    const uint32_t kBl = s2u(Ksl) + (brow * KW + bcol) * 4;
    const uint32_t vBh = s2u(VtH) + (brow * VTW + bcol) * 4;
    const uint32_t vBl = s2u(VtL) + (brow * VTW + bcol) * 4;

    float o[8][4] = {};
    float m0 = -1e30f, m1 = -1e30f, l0 = 0.f, l1 = 0.f;

    for (int t0 = 0; t0 < SEQ; t0 += TT) {
        __syncthreads();
        for (int idx = tid; idx < TT * 32; idx += 128) {
            int r = idx >> 5, w4 = (idx & 31) << 2;
            size_t gb = ((size_t)bh * SEQ + t0 + r) * (NF / 2) + w4;
            *(uint4*)&Ksh[r * KW + w4] = *(const uint4*)&Kh[gb];
            *(uint4*)&Ksl[r * KW + w4] = *(const uint4*)&Kl[gb];
        }
        for (int idx = tid; idx < TT * 16; idx += 128) {
            int t = idx >> 4, d4 = (idx & 15) << 2;
            float4 v = *(const float4*)&V[((size_t)b * SEQ + t0 + t) * DMODEL + h * HD + d4];
            float4 p;
            p.x = __shfl_xor_sync(0xffffffffu, v.x, 16);
            p.y = __shfl_xor_sync(0xffffffffu, v.y, 16);
            p.z = __shfl_xor_sync(0xffffffffu, v.z, 16);
            p.w = __shfl_xor_sync(0xffffffffu, v.w, 16);
            float ve[4], vo[4];
            if (t & 1) {
                ve[0]=p.x; ve[1]=p.y; ve[2]=p.z; ve[3]=p.w;
                vo[0]=v.x; vo[1]=v.y; vo[2]=v.z; vo[3]=v.w;
            } else {
                ve[0]=v.x; ve[1]=v.y; ve[2]=v.z; ve[3]=v.w;
                vo[0]=p.x; vo[1]=p.y; vo[2]=p.z; vo[3]=p.w;
            }
            int i0 = (t & 1) ? 2 : 0;
            int tw = t >> 1;
            #pragma unroll
            for (int i = 0; i < 2; i++) {
                uint32_t hw, lw;
                split_pack(ve[i0 + i], vo[i0 + i], hw, lw);
                VtH[(d4 + i0 + i) * VTW + tw] = hw;
                VtL[(d4 + i0 + i) * VTW + tw] = lw;
            }
        }
        __syncthreads();

        float c[8][4] = {};
        #pragma unroll
        for (int ks = 0; ks < 16; ks++) {
            uint32_t wbb = ks * 32;
            uint32_t bhf[8][2], blf[8][2];
            #pragma unroll
            for (int jj = 0; jj < 4; jj++) {
                uint32_t joff = jj * 16 * KW * 4 + wbb;
                ldsm4(bhf[jj*2][0], bhf[jj*2][1], bhf[jj*2+1][0], bhf[jj*2+1][1], kBh + joff);
                ldsm4(blf[jj*2][0], blf[jj*2][1], blf[jj*2+1][0], blf[jj*2+1][1], kBl + joff);
            }
            #pragma unroll
            for (int n = 0; n < 8; n++)
                mma3(c[n], qfh[ks], qfl[ks], bhf[n], blf[n]);
        }

        float mx0 = -1e30f, mx1 = -1e30f;
        #pragma unroll
        for (int n = 0; n < 8; n++) {
            mx0 = fmaxf(mx0, fmaxf(c[n][0], c[n][1]));
            mx1 = fmaxf(mx1, fmaxf(c[n][2], c[n][3]));
        }
        mx0 = fmaxf(mx0, __shfl_xor_sync(0xffffffffu, mx0, 1));
        mx0 = fmaxf(mx0, __shfl_xor_sync(0xffffffffu, mx0, 2));
        mx1 = fmaxf(mx1, __shfl_xor_sync(0xffffffffu, mx1, 1));
        mx1 = fmaxf(mx1, __shfl_xor_sync(0xffffffffu, mx1, 2));
        float mn0 = fmaxf(m0, mx0 * scale), mn1 = fmaxf(m1, mx1 * scale);
        float a0 = __expf(m0 - mn0), a1 = __expf(m1 - mn1);
        float sum0 = 0.f, sum1 = 0.f;
        #pragma unroll
        for (int n = 0; n < 8; n++) {
            c[n][0] = __expf(fmaf(c[n][0], scale, -mn0));
            c[n][1] = __expf(fmaf(c[n][1], scale, -mn0));
            c[n][2] = __expf(fmaf(c[n][2], scale, -mn1));
            c[n][3] = __expf(fmaf(c[n][3], scale, -mn1));
            sum0 += c[n][0] + c[n][1];
            sum1 += c[n][2] + c[n][3];
        }
        sum0 += __shfl_xor_sync(0xffffffffu, sum0, 1);
        sum0 += __shfl_xor_sync(0xffffffffu, sum0, 2);
        sum1 += __shfl_xor_sync(0xffffffffu, sum1, 1);
        sum1 += __shfl_xor_sync(0xffffffffu, sum1, 2);
        l0 = l0 * a0 + sum0; m0 = mn0;
        l1 = l1 * a1 + sum1; m1 = mn1;

        uint32_t pfh[4][4], pfl[4][4];
        #pragma unroll
        for (int k2 = 0; k2 < 4; k2++) {
            split_pack(c[2*k2  ][0], c[2*k2  ][1], pfh[k2][0], pfl[k2][0]);
            split_pack(c[2*k2  ][2], c[2*k2  ][3], pfh[k2][1], pfl[k2][1]);
            split_pack(c[2*k2+1][0], c[2*k2+1][1], pfh[k2][2], pfl[k2][2]);
            split_pack(c[2*k2+1][2], c[2*k2+1][3], pfh[k2][3], pfl[k2][3]);
        }

        #pragma unroll
        for (int n = 0; n < 8; n++) {
            o[n][0] *= a0; o[n][1] *= a0;
            o[n][2] *= a1; o[n][3] *= a1;
        }
        #pragma unroll
        for (int k2 = 0; k2 < 4; k2++) {
            uint32_t wbb = k2 * 32;
            uint32_t bhf[8][2], blf[8][2];
            #pragma unroll
            for (int jj = 0; jj < 4; jj++) {
                uint32_t joff = jj * 16 * VTW * 4 + wbb;
                ldsm4(bhf[jj*2][0], bhf[jj*2][1], bhf[jj*2+1][0], bhf[jj*2+1][1], vBh + joff);
                ldsm4(blf[jj*2][0], blf[jj*2][1], blf[jj*2+1][0], blf[jj*2+1][1], vBl + joff);
            }
            #pragma unroll
            for (int n = 0; n < 8; n++)
                mma3(o[n], pfh[k2], pfl[k2], bhf[n], blf[n]);
        }
    }

    float inv0 = 1.0f / l0, inv1 = 1.0f / l1;
    int r0 = s0 + warp * 16 + g;
    #pragma unroll
    for (int n = 0; n < 8; n++) {
        int dc = n * 8 + 2 * tig;
        *(float2*)&Ctx[((size_t)b * SEQ + r0) * DMODEL + h * HD + dc] =
            make_float2(o[n][0] * inv0, o[n][1] * inv0);
        *(float2*)&Ctx[((size_t)b * SEQ + r0 + 8) * DMODEL + h * HD + dc] =
            make_float2(o[n][2] * inv1, o[n][3] * inv1);
    }
}

// ---------------- launch ------------------------------------------------------
extern "C" void kernel_launch(void* const* d_in, const int* in_sizes, int n_in,
                              void* d_out, int out_size)
{
    (void)in_sizes; (void)n_in; (void)out_size;
    const float* x  = (const float*)d_in[0];
    const float* Wq = (const float*)d_in[1];
    const float* bq = (const float*)d_in[2];
    const float* Wk = (const float*)d_in[3];
    const float* bk = (const float*)d_in[4];
    const float* Wv = (const float*)d_in[5];
    const float* bv = (const float*)d_in[6];
    const float* Wo = (const float*)d_in[7];
    const float* bo = (const float*)d_in[8];
    const float* P  = (const float*)d_in[9];

    float *q, *k, *v, *ctx;
    uint32_t *qph, *qpl, *kph, *kpl;
    cudaGetSymbolAddress((void**)&q,   g_q);
    cudaGetSymbolAddress((void**)&k,   g_k);
    cudaGetSymbolAddress((void**)&v,   g_v);
    cudaGetSymbolAddress((void**)&ctx, g_ctx);
    cudaGetSymbolAddress((void**)&qph, g_qph);
    cudaGetSymbolAddress((void**)&qpl, g_qpl);
    cudaGetSymbolAddress((void**)&kph, g_kph);
    cudaGetSymbolAddress((void**)&kpl, g_kpl);

    dim3 gemm_grid(DMODEL / 64, MROWS / 128);   // (16, 64)
    gemm_bf3<<<gemm_grid, 256>>>(x, Wq, bq, q, DMODEL, DMODEL);
    gemm_bf3<<<gemm_grid, 256>>>(x, Wk, bk, k, DMODEL, DMODEL);
    gemm_bf3<<<gemm_grid, 256>>>(x, Wv, bv, v, DMODEL, DMODEL);

    const int FP_SMEM = 4 * 128 * FPITCH * 4;    // 73728 B
    cudaFuncSetAttribute(featproj_mma, cudaFuncAttributeMaxDynamicSharedMemorySize, FP_SMEM);
    dim3 fp_grid(NF / 128, MROWS / 128, NHEADS); // (2, 64, 16)
    featproj_mma<<<fp_grid, 256, FP_SMEM>>>(q, P, qph, qpl);
    featproj_mma<<<fp_grid, 256, FP_SMEM>>>(k, P, kph, kpl);

    const int ATT_SMEM = (QT * KW * 2 + 64 * VTW * 2) * 4;   // 86016 B -> 2 CTA/SM
    cudaFuncSetAttribute(attn_bf3, cudaFuncAttributeMaxDynamicSharedMemorySize, ATT_SMEM);
    attn_bf3<<<dim3(SEQ / QT, BH), 128, ATT_SMEM>>>(qph, qpl, kph, kpl, v, ctx);

    gemm_bf3<<<gemm_grid, 256>>>(ctx, Wo, bo, (float*)d_out, DMODEL, DMODEL);
}

// round 13
// speedup vs baseline: 1.1300x; 1.0673x over previous
#include <cuda_runtime.h>
#include <cuda_bf16.h>
#include <math.h>
#include <stdint.h>

#define BATCH  4
#define SEQ    2048
#define DMODEL 1024
#define NHEADS 16
#define HD     64
#define NF     256
#define BH     (BATCH*NHEADS)       // 128
#define MROWS  (BATCH*SEQ)          // 8192

// ---------------- scratch (static device globals; no allocations) ------------
__device__ float g_q  [MROWS*DMODEL];   // [B,S,D]
__device__ float g_k  [MROWS*DMODEL];
__device__ float g_v  [MROWS*DMODEL];
// packed bf16x2 hi/lo buffers
__device__ uint32_t g_xh [(size_t)MROWS*(DMODEL/2)];   // x pre-split
__device__ uint32_t g_xl [(size_t)MROWS*(DMODEL/2)];
__device__ uint32_t g_wh [4ull*DMODEL*(DMODEL/2)];     // Wq,Wk,Wv,Wo pre-split
__device__ uint32_t g_wl [4ull*DMODEL*(DMODEL/2)];
__device__ uint32_t g_ctxh[(size_t)MROWS*(DMODEL/2)];  // attn output pre-split
__device__ uint32_t g_ctxl[(size_t)MROWS*(DMODEL/2)];
__device__ uint32_t g_qph[(size_t)BH*SEQ*(NF/2)];
__device__ uint32_t g_qpl[(size_t)BH*SEQ*(NF/2)];
__device__ uint32_t g_kph[(size_t)BH*SEQ*(NF/2)];
__device__ uint32_t g_kpl[(size_t)BH*SEQ*(NF/2)];

// ---------------- helpers ----------------------------------------------------
__device__ __forceinline__ void split_pack(float x, float y, uint32_t& hi, uint32_t& lo) {
    __nv_bfloat162 h = __floats2bfloat162_rn(x, y);
    float hx = __bfloat162float(h.x);
    float hy = __bfloat162float(h.y);
    __nv_bfloat162 l = __floats2bfloat162_rn(x - hx, y - hy);
    hi = *reinterpret_cast<uint32_t*>(&h);
    lo = *reinterpret_cast<uint32_t*>(&l);
}

__device__ __forceinline__ void mma16(float* c, const uint32_t* a, const uint32_t* b) {
    asm volatile(
        "mma.sync.aligned.m16n8k16.row.col.f32.bf16.bf16.f32 "
        "{%0,%1,%2,%3}, {%4,%5,%6,%7}, {%8,%9}, {%0,%1,%2,%3};\n"
        : "+f"(c[0]), "+f"(c[1]), "+f"(c[2]), "+f"(c[3])
        : "r"(a[0]), "r"(a[1]), "r"(a[2]), "r"(a[3]), "r"(b[0]), "r"(b[1]));
}
__device__ __forceinline__ void mma3(float* c, const uint32_t* ah, const uint32_t* al,
                                     const uint32_t* bh, const uint32_t* bl) {
    mma16(c, ah, bl);
    mma16(c, al, bh);
    mma16(c, ah, bh);
}

__device__ __forceinline__ void ldsm4(uint32_t& r0, uint32_t& r1, uint32_t& r2,
                                      uint32_t& r3, uint32_t addr) {
    asm volatile("ldmatrix.sync.aligned.m8n8.x4.shared.b16 {%0,%1,%2,%3}, [%4];"
        : "=r"(r0), "=r"(r1), "=r"(r2), "=r"(r3) : "r"(addr));
}
__device__ __forceinline__ uint32_t s2u(const void* p) {
    uint32_t a;
    asm("{ .reg .u64 t; cvta.to.shared.u64 t, %1; cvt.u32.u64 %0, t; }" : "=r"(a) : "l"(p));
    return a;
}

// ---------------- split pass: fp32 matrix -> packed bf16 hi/lo ---------------
__global__ __launch_bounds__(256) void split_f32(
    const float* __restrict__ src, uint32_t* __restrict__ oh,
    uint32_t* __restrict__ ol, int nwords)
{
    int i = (blockIdx.x * 256 + threadIdx.x) * 4;
    if (i >= nwords) return;
    float4 a = *(const float4*)&src[2 * i];
    float4 b = *(const float4*)&src[2 * i + 4];
    uint4 h, l;
    split_pack(a.x, a.y, h.x, l.x);
    split_pack(a.z, a.w, h.y, l.y);
    split_pack(b.x, b.y, h.z, l.z);
    split_pack(b.z, b.w, h.w, l.w);
    *(uint4*)&oh[i] = h;
    *(uint4*)&ol[i] = l;
}

// ---------------- bf16x3 GEMM on pre-split inputs ----------------------------
// C[M,N] = A[M,K] @ W[N,K]^T + b.  128x64 tile, BK=32, copy-only fills.
__global__ __launch_bounds__(256) void gemm_bf3p(
    const uint32_t* __restrict__ Ah, const uint32_t* __restrict__ Al,
    const uint32_t* __restrict__ Wh, const uint32_t* __restrict__ Wl,
    const float* __restrict__ bias, float* __restrict__ C,
    int N, int K)
{
    __shared__ uint32_t Ash[128 * 20], Asl[128 * 20];
    __shared__ uint32_t Wsh[64 * 20],  Wsl[64 * 20];
    const int tid  = threadIdx.x;
    const int lane = tid & 31, warp = tid >> 5;
    const int g = lane >> 2, tig = lane & 3;
    const int wq = warp >> 1, wn = warp & 1;
    const int row0 = blockIdx.y * 128, col0 = blockIdx.x * 64;
    const int K2 = K >> 1;

    const int ar = tid >> 1, ak = (tid & 1) * 8;    // A: 128 rows x 16 words
    const int wr = tid >> 2, wk = (tid & 3) * 4;    // W: 64 rows x 16 words

    const int arow = ((lane >> 3) & 1) * 8 + (lane & 7);
    const int acol = (lane >> 4) * 4;
    const int brow = (lane >> 4) * 8 + (lane & 7);
    const int bcol = ((lane >> 3) & 1) * 4;
    uint32_t aOffH[2], aOffL[2], bOffH[2], bOffL[2];
    {
        uint32_t AshU = s2u(Ash), AslU = s2u(Asl), WshU = s2u(Wsh), WslU = s2u(Wsl);
        #pragma unroll
        for (int mi = 0; mi < 2; mi++) {
            uint32_t off = ((wq * 32 + mi * 16 + arow) * 20 + acol) * 4;
            aOffH[mi] = AshU + off;
            aOffL[mi] = AslU + off;
        }
        #pragma unroll
        for (int jj = 0; jj < 2; jj++) {
            uint32_t off = ((wn * 32 + jj * 16 + brow) * 20 + bcol) * 4;
            bOffH[jj] = WshU + off;
            bOffL[jj] = WslU + off;
        }
    }

    float c[2][4][4] = {};

    for (int k0 = 0; k0 < K2; k0 += 16) {
        __syncthreads();
        {
            size_t gb = (size_t)(row0 + ar) * K2 + k0 + ak;
            int w = ar * 20 + ak;
            *(uint4*)&Ash[w    ] = *(const uint4*)&Ah[gb    ];
            *(uint4*)&Ash[w + 4] = *(const uint4*)&Ah[gb + 4];
            *(uint4*)&Asl[w    ] = *(const uint4*)&Al[gb    ];
            *(uint4*)&Asl[w + 4] = *(const uint4*)&Al[gb + 4];
        }
        {
            size_t gb = (size_t)(col0 + wr) * K2 + k0 + wk;
            int w = wr * 20 + wk;
            *(uint4*)&Wsh[w] = *(const uint4*)&Wh[gb];
            *(uint4*)&Wsl[w] = *(const uint4*)&Wl[gb];
        }
        __syncthreads();
        #pragma unroll
        for (int ks = 0; ks < 2; ks++) {
            uint32_t wbb = ks * 32;
            uint32_t ah[2][4], al[2][4], bh[4][2], bl[4][2];
            #pragma unroll
            for (int mi = 0; mi < 2; mi++) {
                ldsm4(ah[mi][0], ah[mi][1], ah[mi][2], ah[mi][3], aOffH[mi] + wbb);
                ldsm4(al[mi][0], al[mi][1], al[mi][2], al[mi][3], aOffL[mi] + wbb);
            }
            #pragma unroll
            for (int jj = 0; jj < 2; jj++) {
                ldsm4(bh[jj*2][0], bh[jj*2][1], bh[jj*2+1][0], bh[jj*2+1][1], bOffH[jj] + wbb);
                ldsm4(bl[jj*2][0], bl[jj*2][1], bl[jj*2+1][0], bl[jj*2+1][1], bOffL[jj] + wbb);
            }
            #pragma unroll
            for (int mi = 0; mi < 2; mi++)
                #pragma unroll
                for (int n = 0; n < 4; n++)
                    mma3(c[mi][n], ah[mi], al[mi], bh[n], bl[n]);
        }
    }
    #pragma unroll
    for (int mi = 0; mi < 2; mi++) {
        #pragma unroll
        for (int n = 0; n < 4; n++) {
            int col = col0 + wn * 32 + n * 8 + 2 * tig;
            float b0 = bias[col], b1 = bias[col + 1];
            int r0 = row0 + wq * 32 + mi * 16 + g;
            *(float2*)&C[(size_t)r0 * N + col] =
                make_float2(c[mi][n][0] + b0, c[mi][n][1] + b1);
            *(float2*)&C[(size_t)(r0 + 8) * N + col] =
                make_float2(c[mi][n][2] + b0, c[mi][n][3] + b1);
        }
    }
}

// ---------------- feature projection (bf16x3 MMA; known-good) ----------------
#define FPITCH 36
__global__ __launch_bounds__(256) void featproj_mma(
    const float* __restrict__ In, const float* __restrict__ P,
    uint32_t* __restrict__ Oh, uint32_t* __restrict__ Ol)
{
    extern __shared__ uint32_t fsm[];
    uint32_t* Ash = fsm;                    // 128*36
    uint32_t* Asl = Ash + 128 * FPITCH;
    uint32_t* Wsh = Asl + 128 * FPITCH;
    uint32_t* Wsl = Wsh + 128 * FPITCH;

    const int tid  = threadIdx.x;
    const int lane = tid & 31, warp = tid >> 5;
    const int g = lane >> 2, tig = lane & 3;
    const int wq = warp >> 1, wn = warp & 1;
    const int h = blockIdx.z;
    const int row0 = blockIdx.y * 128, col0 = blockIdx.x * 128;

    const int ar = tid >> 1, ak = (tid & 1) * 32;

    {
        const float* src = In + (size_t)(row0 + ar) * DMODEL + h * HD + ak;
        int w = ar * FPITCH + (ak >> 1);
        #pragma unroll
        for (int i = 0; i < 8; i++) {
            float4 v = *(const float4*)(src + i * 4);
            split_pack(v.x, v.y, Ash[w + 2 * i], Asl[w + 2 * i]);
            split_pack(v.z, v.w, Ash[w + 2 * i + 1], Asl[w + 2 * i + 1]);
        }
    }
    {
        const float* src = P + (size_t)(col0 + ar) * HD + ak;
        int w = ar * FPITCH + (ak >> 1);
        #pragma unroll
        for (int i = 0; i < 8; i++) {
            float4 v = *(const float4*)(src + i * 4);
            split_pack(v.x, v.y, Wsh[w + 2 * i], Wsl[w + 2 * i]);
            split_pack(v.z, v.w, Wsh[w + 2 * i + 1], Wsl[w + 2 * i + 1]);
        }
    }
    __syncthreads();

    const int arow = ((lane >> 3) & 1) * 8 + (lane & 7);
    const int acol = (lane >> 4) * 4;
    const int brow = (lane >> 4) * 8 + (lane & 7);
    const int bcol = ((lane >> 3) & 1) * 4;

    float c[2][8][4] = {};
    #pragma unroll
    for (int ks = 0; ks < 4; ks++) {
        uint32_t wbb = ks * 32;
        uint32_t ah[2][4], al[2][4], bh[8][2], bl[8][2];
        #pragma unroll
        for (int mi = 0; mi < 2; mi++) {
            uint32_t off = ((wq * 32 + mi * 16 + arow) * FPITCH + acol) * 4 + wbb;
            ldsm4(ah[mi][0], ah[mi][1], ah[mi][2], ah[mi][3], s2u(Ash) + off);
            ldsm4(al[mi][0], al[mi][1], al[mi][2], al[mi][3], s2u(Asl) + off);
        }
        #pragma unroll
        for (int jj = 0; jj < 4; jj++) {
            uint32_t off = ((wn * 64 + jj * 16 + brow) * FPITCH + bcol) * 4 + wbb;
            ldsm4(bh[jj*2][0], bh[jj*2][1], bh[jj*2+1][0], bh[jj*2+1][1], s2u(Wsh) + off);
            ldsm4(bl[jj*2][0], bl[jj*2][1], bl[jj*2+1][0], bl[jj*2+1][1], s2u(Wsl) + off);
        }
        #pragma unroll
        for (int mi = 0; mi < 2; mi++)
            #pragma unroll
            for (int n = 0; n < 8; n++)
                mma3(c[mi][n], ah[mi], al[mi], bh[n], bl[n]);
    }

    #pragma unroll
    for (int mi = 0; mi < 2; mi++) {
        #pragma unroll
        for (int n = 0; n < 8; n++) {
            int col = col0 + wn * 64 + n * 8 + 2 * tig;
            int m0 = row0 + wq * 32 + mi * 16 + g;
            int b0 = m0 >> 11, s0 = m0 & 2047;
            size_t base0 = ((size_t)(b0 * NHEADS + h) * SEQ + s0) * (NF / 2) + (col >> 1);
            split_pack(c[mi][n][0], c[mi][n][1], Oh[base0], Ol[base0]);
            int m1 = m0 + 8;
            int b1 = m1 >> 11, s1 = m1 & 2047;
            size_t base1 = ((size_t)(b1 * NHEADS + h) * SEQ + s1) * (NF / 2) + (col >> 1);
            split_pack(c[mi][n][2], c[mi][n][3], Oh[base1], Ol[base1]);
        }
    }
}

// ---------------- flash attention (round-8 core; epilogue writes split ctx) --
#define QT 64
#define TT 64
#define KW 132        // K tile pitch (words): NF/2 + 4
#define VTW 36        // V^T pitch (words): TT/2 + 4

__global__ __launch_bounds__(128) void attn_bf3(
    const uint32_t* __restrict__ Qh, const uint32_t* __restrict__ Ql,
    const uint32_t* __restrict__ Kh, const uint32_t* __restrict__ Kl,
    const float* __restrict__ V,
    uint32_t* __restrict__ CtxH, uint32_t* __restrict__ CtxL)
{
    extern __shared__ uint32_t smw[];
    uint32_t* Ksh = smw;                    // 64*132
    uint32_t* Ksl = Ksh + QT * KW;
    uint32_t* VtH = Ksl + QT * KW;          // 64*36
    uint32_t* VtL = VtH + 64 * VTW;

    const int tid  = threadIdx.x;
    const int lane = tid & 31, warp = tid >> 5;       // warp 0..3
    const int g = lane >> 2, tig = lane & 3;
    const int bh = blockIdx.y, b = bh >> 4, h = bh & 15;
    const int s0 = blockIdx.x * QT;
    const float scale = 0.0625f;   // 1/sqrt(256)

    const int arow = ((lane >> 3) & 1) * 8 + (lane & 7);
    const int acol = (lane >> 4) * 4;
    const int brow = (lane >> 4) * 8 + (lane & 7);
    const int bcol = ((lane >> 3) & 1) * 4;

    // ---- stage Q tile into K buffers, then load A-frags to registers ----
    for (int idx = tid; idx < QT * 32; idx += 128) {
        int r = idx >> 5, w4 = (idx & 31) << 2;
        size_t gb = ((size_t)bh * SEQ + s0 + r) * (NF / 2) + w4;
        *(uint4*)&Ksh[r * KW + w4] = *(const uint4*)&Qh[gb];
        *(uint4*)&Ksl[r * KW + w4] = *(const uint4*)&Ql[gb];
    }
    __syncthreads();
    uint32_t qfh[16][4], qfl[16][4];
    {
        uint32_t baseH = s2u(Ksh) + ((warp * 16 + arow) * KW + acol) * 4;
        uint32_t baseL = s2u(Ksl) + ((warp * 16 + arow) * KW + acol) * 4;
        #pragma unroll
        for (int ks = 0; ks < 16; ks++) {
            ldsm4(qfh[ks][0], qfh[ks][1], qfh[ks][2], qfh[ks][3], baseH + ks * 32);
            ldsm4(qfl[ks][0], qfl[ks][1], qfl[ks][2], qfl[ks][3], baseL + ks * 32);
        }
    }

    const uint32_t kBh = s2u(Ksh) + (brow * KW + bcol) * 4;
    const uint32_t kBl = s2u(Ksl) + (brow * KW + bcol) * 4;
    const uint32_t vBh = s2u(VtH) + (brow * VTW + bcol) * 4;
    const uint32_t vBl = s2u(VtL) + (brow * VTW + bcol) * 4;

    float o[8][4] = {};
    float m0 = -1e30f, m1 = -1e30f, l0 = 0.f, l1 = 0.f;

    for (int t0 = 0; t0 < SEQ; t0 += TT) {
        __syncthreads();
        for (int idx = tid; idx < TT * 32; idx += 128) {
            int r = idx >> 5, w4 = (idx & 31) << 2;
            size_t gb = ((size_t)bh * SEQ + t0 + r) * (NF / 2) + w4;
            *(uint4*)&Ksh[r * KW + w4] = *(const uint4*)&Kh[gb];
            *(uint4*)&Ksl[r * KW + w4] = *(const uint4*)&Kl[gb];
        }
        for (int idx = tid; idx < TT * 16; idx += 128) {
            int t = idx >> 4, d4 = (idx & 15) << 2;
            float4 v = *(const float4*)&V[((size_t)b * SEQ + t0 + t) * DMODEL + h * HD + d4];
            float4 p;
            p.x = __shfl_xor_sync(0xffffffffu, v.x, 16);
            p.y = __shfl_xor_sync(0xffffffffu, v.y, 16);
            p.z = __shfl_xor_sync(0xffffffffu, v.z, 16);
            p.w = __shfl_xor_sync(0xffffffffu, v.w, 16);
            float ve[4], vo[4];
            if (t & 1) {
                ve[0]=p.x; ve[1]=p.y; ve[2]=p.z; ve[3]=p.w;
                vo[0]=v.x; vo[1]=v.y; vo[2]=v.z; vo[3]=v.w;
            } else {
                ve[0]=v.x; ve[1]=v.y; ve[2]=v.z; ve[3]=v.w;
                vo[0]=p.x; vo[1]=p.y; vo[2]=p.z; vo[3]=p.w;
            }
            int i0 = (t & 1) ? 2 : 0;
            int tw = t >> 1;
            #pragma unroll
            for (int i = 0; i < 2; i++) {
                uint32_t hw, lw;
                split_pack(ve[i0 + i], vo[i0 + i], hw, lw);
                VtH[(d4 + i0 + i) * VTW + tw] = hw;
                VtL[(d4 + i0 + i) * VTW + tw] = lw;
            }
        }
        __syncthreads();

        float c[8][4] = {};
        #pragma unroll
        for (int ks = 0; ks < 16; ks++) {
            uint32_t wbb = ks * 32;
            uint32_t bhf[8][2], blf[8][2];
            #pragma unroll
            for (int jj = 0; jj < 4; jj++) {
                uint32_t joff = jj * 16 * KW * 4 + wbb;
                ldsm4(bhf[jj*2][0], bhf[jj*2][1], bhf[jj*2+1][0], bhf[jj*2+1][1], kBh + joff);
                ldsm4(blf[jj*2][0], blf[jj*2][1], blf[jj*2+1][0], blf[jj*2+1][1], kBl + joff);
            }
            #pragma unroll
            for (int n = 0; n < 8; n++)
                mma3(c[n], qfh[ks], qfl[ks], bhf[n], blf[n]);
        }

        float mx0 = -1e30f, mx1 = -1e30f;
        #pragma unroll
        for (int n = 0; n < 8; n++) {
            mx0 = fmaxf(mx0, fmaxf(c[n][0], c[n][1]));
            mx1 = fmaxf(mx1, fmaxf(c[n][2], c[n][3]));
        }
        mx0 = fmaxf(mx0, __shfl_xor_sync(0xffffffffu, mx0, 1));
        mx0 = fmaxf(mx0, __shfl_xor_sync(0xffffffffu, mx0, 2));
        mx1 = fmaxf(mx1, __shfl_xor_sync(0xffffffffu, mx1, 1));
        mx1 = fmaxf(mx1, __shfl_xor_sync(0xffffffffu, mx1, 2));
        float mn0 = fmaxf(m0, mx0 * scale), mn1 = fmaxf(m1, mx1 * scale);
        float a0 = __expf(m0 - mn0), a1 = __expf(m1 - mn1);
        float sum0 = 0.f, sum1 = 0.f;
        #pragma unroll
        for (int n = 0; n < 8; n++) {
            c[n][0] = __expf(fmaf(c[n][0], scale, -mn0));
            c[n][1] = __expf(fmaf(c[n][1], scale, -mn0));
            c[n][2] = __expf(fmaf(c[n][2], scale, -mn1));
            c[n][3] = __expf(fmaf(c[n][3], scale, -mn1));
            sum0 += c[n][0] + c[n][1];
            sum1 += c[n][2] + c[n][3];
        }
        sum0 += __shfl_xor_sync(0xffffffffu, sum0, 1);
        sum0 += __shfl_xor_sync(0xffffffffu, sum0, 2);
        sum1 += __shfl_xor_sync(0xffffffffu, sum1, 1);
        sum1 += __shfl_xor_sync(0xffffffffu, sum1, 2);
        l0 = l0 * a0 + sum0; m0 = mn0;
        l1 = l1 * a1 + sum1; m1 = mn1;

        uint32_t pfh[4][4], pfl[4][4];
        #pragma unroll
        for (int k2 = 0; k2 < 4; k2++) {
            split_pack(c[2*k2  ][0], c[2*k2  ][1], pfh[k2][0], pfl[k2][0]);
            split_pack(c[2*k2  ][2], c[2*k2  ][3], pfh[k2][1], pfl[k2][1]);
            split_pack(c[2*k2+1][0], c[2*k2+1][1], pfh[k2][2], pfl[k2][2]);
            split_pack(c[2*k2+1][2], c[2*k2+1][3], pfh[k2][3], pfl[k2][3]);
        }

        #pragma unroll
        for (int n = 0; n < 8; n++) {
            o[n][0] *= a0; o[n][1] *= a0;
            o[n][2] *= a1; o[n][3] *= a1;
        }
        #pragma unroll
        for (int k2 = 0; k2 < 4; k2++) {
            uint32_t wbb = k2 * 32;
            uint32_t bhf[8][2], blf[8][2];
            #pragma unroll
            for (int jj = 0; jj < 4; jj++) {
                uint32_t joff = jj * 16 * VTW * 4 + wbb;
                ldsm4(bhf[jj*2][0], bhf[jj*2][1], bhf[jj*2+1][0], bhf[jj*2+1][1], vBh + joff);
                ldsm4(blf[jj*2][0], blf[jj*2][1], blf[jj*2+1][0], blf[jj*2+1][1], vBl + joff);
            }
            #pragma unroll
            for (int n = 0; n < 8; n++)
                mma3(o[n], pfh[k2], pfl[k2], bhf[n], blf[n]);
        }
    }

    // ---- epilogue: write ctx pre-split (packed bf16 hi/lo) ----
    float inv0 = 1.0f / l0, inv1 = 1.0f / l1;
    int r0 = s0 + warp * 16 + g;
    #pragma unroll
    for (int n = 0; n < 8; n++) {
        int dc = n * 8 + 2 * tig;
        size_t w0 = (((size_t)b * SEQ + r0) * DMODEL + h * HD + dc) >> 1;
        size_t w1 = (((size_t)b * SEQ + r0 + 8) * DMODEL + h * HD + dc) >> 1;
        split_pack(o[n][0] * inv0, o[n][1] * inv0, CtxH[w0], CtxL[w0]);
        split_pack(o[n][2] * inv1, o[n][3] * inv1, CtxH[w1], CtxL[w1]);
    }
}

// ---------------- launch ------------------------------------------------------
extern "C" void kernel_launch(void* const* d_in, const int* in_sizes, int n_in,
                              void* d_out, int out_size)
{
    (void)in_sizes; (void)n_in; (void)out_size;
    const float* x  = (const float*)d_in[0];
    const float* Wq = (const float*)d_in[1];
    const float* bq = (const float*)d_in[2];
    const float* Wk = (const float*)d_in[3];
    const float* bk = (const float*)d_in[4];
    const float* Wv = (const float*)d_in[5];
    const float* bv = (const float*)d_in[6];
    const float* Wo = (const float*)d_in[7];
    const float* bo = (const float*)d_in[8];
    const float* P  = (const float*)d_in[9];

    float *q, *k, *v;
    uint32_t *xh, *xl, *wh, *wl, *ctxh, *ctxl, *qph, *qpl, *kph, *kpl;
    cudaGetSymbolAddress((void**)&q,    g_q);
    cudaGetSymbolAddress((void**)&k,    g_k);
    cudaGetSymbolAddress((void**)&v,    g_v);
    cudaGetSymbolAddress((void**)&xh,   g_xh);
    cudaGetSymbolAddress((void**)&xl,   g_xl);
    cudaGetSymbolAddress((void**)&wh,   g_wh);
    cudaGetSymbolAddress((void**)&wl,   g_wl);
    cudaGetSymbolAddress((void**)&ctxh, g_ctxh);
    cudaGetSymbolAddress((void**)&ctxl, g_ctxl);
    cudaGetSymbolAddress((void**)&qph,  g_qph);
    cudaGetSymbolAddress((void**)&qpl,  g_qpl);
    cudaGetSymbolAddress((void**)&kph,  g_kph);
    cudaGetSymbolAddress((void**)&kpl,  g_kpl);

    const int WW = DMODEL * (DMODEL / 2);   // words per weight matrix
    // pre-split x and the four weight matrices
    split_f32<<<(MROWS * (DMODEL / 2)) / 1024, 256>>>(x, xh, xl, MROWS * (DMODEL / 2));
    split_f32<<<WW / 1024, 256>>>(Wq, wh + 0ull * WW, wl + 0ull * WW, WW);
    split_f32<<<WW / 1024, 256>>>(Wk, wh + 1ull * WW, wl + 1ull * WW, WW);
    split_f32<<<WW / 1024, 256>>>(Wv, wh + 2ull * WW, wl + 2ull * WW, WW);
    split_f32<<<WW / 1024, 256>>>(Wo, wh + 3ull * WW, wl + 3ull * WW, WW);

    dim3 gemm_grid(DMODEL / 64, MROWS / 128);   // (16, 64)
    gemm_bf3p<<<gemm_grid, 256>>>(xh, xl, wh + 0ull * WW, wl + 0ull * WW, bq, q, DMODEL, DMODEL);
    gemm_bf3p<<<gemm_grid, 256>>>(xh, xl, wh + 1ull * WW, wl + 1ull * WW, bk, k, DMODEL, DMODEL);
    gemm_bf3p<<<gemm_grid, 256>>>(xh, xl, wh + 2ull * WW, wl + 2ull * WW, bv, v, DMODEL, DMODEL);

    const int FP_SMEM = 4 * 128 * FPITCH * 4;    // 73728 B
    cudaFuncSetAttribute(featproj_mma, cudaFuncAttributeMaxDynamicSharedMemorySize, FP_SMEM);
    dim3 fp_grid(NF / 128, MROWS / 128, NHEADS); // (2, 64, 16)
    featproj_mma<<<fp_grid, 256, FP_SMEM>>>(q, P, qph, qpl);
    featproj_mma<<<fp_grid, 256, FP_SMEM>>>(k, P, kph, kpl);

    const int ATT_SMEM = (QT * KW * 2 + 64 * VTW * 2) * 4;   // 86016 B -> 2 CTA/SM
    cudaFuncSetAttribute(attn_bf3, cudaFuncAttributeMaxDynamicSharedMemorySize, ATT_SMEM);
    attn_bf3<<<dim3(SEQ / QT, BH), 128, ATT_SMEM>>>(qph, qpl, kph, kpl, v, ctxh, ctxl);

    gemm_bf3p<<<gemm_grid, 256>>>(ctxh, ctxl, wh + 3ull * WW, wl + 3ull * WW, bo,
                                  (float*)d_out, DMODEL, DMODEL);
}

// round 15
// speedup vs baseline: 1.1939x; 1.0566x over previous
#include <cuda_runtime.h>
#include <cuda_bf16.h>
#include <math.h>
#include <stdint.h>

#define BATCH  4
#define SEQ    2048
#define DMODEL 1024
#define NHEADS 16
#define HD     64
#define NF     256
#define BH     (BATCH*NHEADS)       // 128
#define MROWS  (BATCH*SEQ)          // 8192

// ---------------- scratch (static device globals; no allocations) ------------
__device__ float g_q  [MROWS*DMODEL];   // [B,S,D]
__device__ float g_k  [MROWS*DMODEL];
__device__ float g_v  [MROWS*DMODEL];
// packed bf16x2 hi/lo buffers
__device__ uint32_t g_xh [(size_t)MROWS*(DMODEL/2)];   // x pre-split
__device__ uint32_t g_xl [(size_t)MROWS*(DMODEL/2)];
__device__ uint32_t g_wh [4ull*DMODEL*(DMODEL/2)];     // Wq,Wk,Wv,Wo pre-split
__device__ uint32_t g_wl [4ull*DMODEL*(DMODEL/2)];
__device__ uint32_t g_ctxh[(size_t)MROWS*(DMODEL/2)];  // attn output pre-split
__device__ uint32_t g_ctxl[(size_t)MROWS*(DMODEL/2)];
__device__ uint32_t g_qph[(size_t)BH*SEQ*(NF/2)];
__device__ uint32_t g_qpl[(size_t)BH*SEQ*(NF/2)];
__device__ uint32_t g_kph[(size_t)BH*SEQ*(NF/2)];
__device__ uint32_t g_kpl[(size_t)BH*SEQ*(NF/2)];

// ---------------- helpers ----------------------------------------------------
__device__ __forceinline__ void split_pack(float x, float y, uint32_t& hi, uint32_t& lo) {
    __nv_bfloat162 h = __floats2bfloat162_rn(x, y);
    float hx = __bfloat162float(h.x);
    float hy = __bfloat162float(h.y);
    __nv_bfloat162 l = __floats2bfloat162_rn(x - hx, y - hy);
    hi = *reinterpret_cast<uint32_t*>(&h);
    lo = *reinterpret_cast<uint32_t*>(&l);
}

__device__ __forceinline__ void mma16(float* c, const uint32_t* a, const uint32_t* b) {
    asm volatile(
        "mma.sync.aligned.m16n8k16.row.col.f32.bf16.bf16.f32 "
        "{%0,%1,%2,%3}, {%4,%5,%6,%7}, {%8,%9}, {%0,%1,%2,%3};\n"
        : "+f"(c[0]), "+f"(c[1]), "+f"(c[2]), "+f"(c[3])
        : "r"(a[0]), "r"(a[1]), "r"(a[2]), "r"(a[3]), "r"(b[0]), "r"(b[1]));
}
__device__ __forceinline__ void mma3(float* c, const uint32_t* ah, const uint32_t* al,
                                     const uint32_t* bh, const uint32_t* bl) {
    mma16(c, ah, bl);
    mma16(c, al, bh);
    mma16(c, ah, bh);
}

__device__ __forceinline__ void ldsm4(uint32_t& r0, uint32_t& r1, uint32_t& r2,
                                      uint32_t& r3, uint32_t addr) {
    asm volatile("ldmatrix.sync.aligned.m8n8.x4.shared.b16 {%0,%1,%2,%3}, [%4];"
        : "=r"(r0), "=r"(r1), "=r"(r2), "=r"(r3) : "r"(addr));
}
__device__ __forceinline__ uint32_t s2u(const void* p) {
    uint32_t a;
    asm("{ .reg .u64 t; cvta.to.shared.u64 t, %1; cvt.u32.u64 %0, t; }" : "=r"(a) : "l"(p));
    return a;
}
__device__ __forceinline__ void cpa16(uint32_t dst, const void* src) {
    asm volatile("cp.async.cg.shared.global [%0], [%1], 16;" :: "r"(dst), "l"(src));
}
#define CP_COMMIT() asm volatile("cp.async.commit_group;" ::: "memory")
#define CP_WAIT0()  asm volatile("cp.async.wait_group 0;" ::: "memory")

// ---------------- split pass: fp32 matrix -> packed bf16 hi/lo ---------------
__global__ __launch_bounds__(256) void split_f32(
    const float* __restrict__ src, uint32_t* __restrict__ oh,
    uint32_t* __restrict__ ol, int nwords)
{
    int i = (blockIdx.x * 256 + threadIdx.x) * 4;
    if (i >= nwords) return;
    float4 a = *(const float4*)&src[2 * i];
    float4 b = *(const float4*)&src[2 * i + 4];
    uint4 h, l;
    split_pack(a.x, a.y, h.x, l.x);
    split_pack(a.z, a.w, h.y, l.y);
    split_pack(b.x, b.y, h.z, l.z);
    split_pack(b.z, b.w, h.w, l.w);
    *(uint4*)&oh[i] = h;
    *(uint4*)&ol[i] = l;
}

// ---------------- bf16x3 GEMM, pre-split inputs, cp.async 2-stage ------------
// C[M,N] = A[M,K] @ W[N,K]^T + b.  128x64 tile, BK=32 (16 words), KT=K/32 iters.
// Stage layout (words): Ash@0 Asl@2560 Wsh@5120 Wsl@6400; SOFF=7680/stage.
#define GSOFF 7680
__global__ __launch_bounds__(256) void gemm_bf3p(
    const uint32_t* __restrict__ Ah, const uint32_t* __restrict__ Al,
    const uint32_t* __restrict__ Wh, const uint32_t* __restrict__ Wl,
    const float* __restrict__ bias, float* __restrict__ C,
    int N, int K)
{
    extern __shared__ uint32_t gsm[];
    const int tid  = threadIdx.x;
    const int lane = tid & 31, warp = tid >> 5;
    const int g = lane >> 2, tig = lane & 3;
    const int wq = warp >> 1, wn = warp & 1;
    const int row0 = blockIdx.y * 128, col0 = blockIdx.x * 64;
    const int K2 = K >> 1;
    const int KT = K2 >> 4;   // #32-float slabs

    const int ar = tid >> 1, ak = (tid & 1) * 8;    // A loader: 128 rows x 16 words
    const int wr = tid >> 2, wk = (tid & 3) * 4;    // W loader: 64 rows x 16 words
    const uint32_t smb = s2u(gsm);

    // per-thread cp.async smem byte offsets (stage 0)
    const uint32_t aOff = smb + (ar * 20 + ak) * 4;
    const uint32_t wOff = smb + (5120 + wr * 20 + wk) * 4;
    const uint32_t* Agp = Ah + (size_t)(row0 + ar) * K2 + ak;
    const uint32_t* Algp = Al + (size_t)(row0 + ar) * K2 + ak;
    const uint32_t* Wgp = Wh + (size_t)(col0 + wr) * K2 + wk;
    const uint32_t* Wlgp = Wl + (size_t)(col0 + wr) * K2 + wk;

    // ldmatrix per-lane byte offsets (stage 0)
    const int arow = ((lane >> 3) & 1) * 8 + (lane & 7);
    const int acol = (lane >> 4) * 4;
    const int brow = (lane >> 4) * 8 + (lane & 7);
    const int bcol = ((lane >> 3) & 1) * 4;
    uint32_t aLdH[2], aLdL[2], bLdH[2], bLdL[2];
    #pragma unroll
    for (int mi = 0; mi < 2; mi++) {
        uint32_t off = ((wq * 32 + mi * 16 + arow) * 20 + acol) * 4;
        aLdH[mi] = smb + off;
        aLdL[mi] = smb + 2560 * 4 + off;
    }
    #pragma unroll
    for (int jj = 0; jj < 2; jj++) {
        uint32_t off = ((wn * 32 + jj * 16 + brow) * 20 + bcol) * 4;
        bLdH[jj] = smb + 5120 * 4 + off;
        bLdL[jj] = smb + 6400 * 4 + off;
    }

    float c[2][4][4] = {};

    // issue slab 0 into stage 0
    {
        cpa16(aOff,                     Agp);
        cpa16(aOff + 16,                Agp + 4);
        cpa16(aOff + 2560 * 4,          Algp);
        cpa16(aOff + 2560 * 4 + 16,     Algp + 4);
        cpa16(wOff,                     Wgp);
        cpa16(wOff + 1280 * 4,          Wlgp);
    }
    CP_COMMIT();

    for (int kt = 0; kt < KT; kt++) {
        const int s = kt & 1;
        const uint32_t sb = (uint32_t)s * GSOFF * 4;
        CP_WAIT0();
        __syncthreads();
        if (kt + 1 < KT) {
            const uint32_t nb = (uint32_t)((s ^ 1) * GSOFF) * 4;
            int kw = (kt + 1) * 16;
            cpa16(aOff + nb,                 Agp + kw);
            cpa16(aOff + nb + 16,            Agp + kw + 4);
            cpa16(aOff + nb + 2560 * 4,      Algp + kw);
            cpa16(aOff + nb + 2560 * 4 + 16, Algp + kw + 4);
            cpa16(wOff + nb,                 Wgp + kw);
            cpa16(wOff + nb + 1280 * 4,      Wlgp + kw);
            CP_COMMIT();
        }
        #pragma unroll
        for (int ks = 0; ks < 2; ks++) {
            uint32_t wbb = sb + ks * 32;
            uint32_t ah[2][4], al[2][4], bh[4][2], bl[4][2];
            #pragma unroll
            for (int mi = 0; mi < 2; mi++) {
                ldsm4(ah[mi][0], ah[mi][1], ah[mi][2], ah[mi][3], aLdH[mi] + wbb);
                ldsm4(al[mi][0], al[mi][1], al[mi][2], al[mi][3], aLdL[mi] + wbb);
            }
            #pragma unroll
            for (int jj = 0; jj < 2; jj++) {
                ldsm4(bh[jj*2][0], bh[jj*2][1], bh[jj*2+1][0], bh[jj*2+1][1], bLdH[jj] + wbb);
                ldsm4(bl[jj*2][0], bl[jj*2][1], bl[jj*2+1][0], bl[jj*2+1][1], bLdL[jj] + wbb);
            }
            #pragma unroll
            for (int mi = 0; mi < 2; mi++)
                #pragma unroll
                for (int n = 0; n < 4; n++)
                    mma3(c[mi][n], ah[mi], al[mi], bh[n], bl[n]);
        }
    }
    #pragma unroll
    for (int mi = 0; mi < 2; mi++) {
        #pragma unroll
        for (int n = 0; n < 4; n++) {
            int col = col0 + wn * 32 + n * 8 + 2 * tig;
            float b0 = bias[col], b1 = bias[col + 1];
            int r0 = row0 + wq * 32 + mi * 16 + g;
            *(float2*)&C[(size_t)r0 * N + col] =
                make_float2(c[mi][n][0] + b0, c[mi][n][1] + b1);
            *(float2*)&C[(size_t)(r0 + 8) * N + col] =
                make_float2(c[mi][n][2] + b0, c[mi][n][3] + b1);
        }
    }
}

// ---------------- feature projection (bf16x3 MMA; known-good) ----------------
#define FPITCH 36
__global__ __launch_bounds__(256) void featproj_mma(
    const float* __restrict__ In, const float* __restrict__ P,
    uint32_t* __restrict__ Oh, uint32_t* __restrict__ Ol)
{
    extern __shared__ uint32_t fsm[];
    uint32_t* Ash = fsm;                    // 128*36
    uint32_t* Asl = Ash + 128 * FPITCH;
    uint32_t* Wsh = Asl + 128 * FPITCH;
    uint32_t* Wsl = Wsh + 128 * FPITCH;

    const int tid  = threadIdx.x;
    const int lane = tid & 31, warp = tid >> 5;
    const int g = lane >> 2, tig = lane & 3;
    const int wq = warp >> 1, wn = warp & 1;
    const int h = blockIdx.z;
    const int row0 = blockIdx.y * 128, col0 = blockIdx.x * 128;

    const int ar = tid >> 1, ak = (tid & 1) * 32;

    {
        const float* src = In + (size_t)(row0 + ar) * DMODEL + h * HD + ak;
        int w = ar * FPITCH + (ak >> 1);
        #pragma unroll
        for (int i = 0; i < 8; i++) {
            float4 v = *(const float4*)(src + i * 4);
            split_pack(v.x, v.y, Ash[w + 2 * i], Asl[w + 2 * i]);
            split_pack(v.z, v.w, Ash[w + 2 * i + 1], Asl[w + 2 * i + 1]);
        }
    }
    {
        const float* src = P + (size_t)(col0 + ar) * HD + ak;
        int w = ar * FPITCH + (ak >> 1);
        #pragma unroll
        for (int i = 0; i < 8; i++) {
            float4 v = *(const float4*)(src + i * 4);
            split_pack(v.x, v.y, Wsh[w + 2 * i], Wsl[w + 2 * i]);
            split_pack(v.z, v.w, Wsh[w + 2 * i + 1], Wsl[w + 2 * i + 1]);
        }
    }
    __syncthreads();

    const int arow = ((lane >> 3) & 1) * 8 + (lane & 7);
    const int acol = (lane >> 4) * 4;
    const int brow = (lane >> 4) * 8 + (lane & 7);
    const int bcol = ((lane >> 3) & 1) * 4;

    float c[2][8][4] = {};
    #pragma unroll
    for (int ks = 0; ks < 4; ks++) {
        uint32_t wbb = ks * 32;
        uint32_t ah[2][4], al[2][4], bh[8][2], bl[8][2];
        #pragma unroll
        for (int mi = 0; mi < 2; mi++) {
            uint32_t off = ((wq * 32 + mi * 16 + arow) * FPITCH + acol) * 4 + wbb;
            ldsm4(ah[mi][0], ah[mi][1], ah[mi][2], ah[mi][3], s2u(Ash) + off);
            ldsm4(al[mi][0], al[mi][1], al[mi][2], al[mi][3], s2u(Asl) + off);
        }
        #pragma unroll
        for (int jj = 0; jj < 4; jj++) {
            uint32_t off = ((wn * 64 + jj * 16 + brow) * FPITCH + bcol) * 4 + wbb;
            ldsm4(bh[jj*2][0], bh[jj*2][1], bh[jj*2+1][0], bh[jj*2+1][1], s2u(Wsh) + off);
            ldsm4(bl[jj*2][0], bl[jj*2][1], bl[jj*2+1][0], bl[jj*2+1][1], s2u(Wsl) + off);
        }
        #pragma unroll
        for (int mi = 0; mi < 2; mi++)
            #pragma unroll
            for (int n = 0; n < 8; n++)
                mma3(c[mi][n], ah[mi], al[mi], bh[n], bl[n]);
    }

    #pragma unroll
    for (int mi = 0; mi < 2; mi++) {
        #pragma unroll
        for (int n = 0; n < 8; n++) {
            int col = col0 + wn * 64 + n * 8 + 2 * tig;
            int m0 = row0 + wq * 32 + mi * 16 + g;
            int b0 = m0 >> 11, s0 = m0 & 2047;
            size_t base0 = ((size_t)(b0 * NHEADS + h) * SEQ + s0) * (NF / 2) + (col >> 1);
            split_pack(c[mi][n][0], c[mi][n][1], Oh[base0], Ol[base0]);
            int m1 = m0 + 8;
            int b1 = m1 >> 11, s1 = m1 & 2047;
            size_t base1 = ((size_t)(b1 * NHEADS + h) * SEQ + s1) * (NF / 2) + (col >> 1);
            split_pack(c[mi][n][2], c[mi][n][3], Oh[base1], Ol[base1]);
        }
    }
}

// ---------------- flash attention (round-8 core; epilogue writes split ctx) --
#define QT 64
#define TT 64
#define KW 132        // K tile pitch (words): NF/2 + 4
#define VTW 36        // V^T pitch (words): TT/2 + 4

__global__ __launch_bounds__(128) void attn_bf3(
    const uint32_t* __restrict__ Qh, const uint32_t* __restrict__ Ql,
    const uint32_t* __restrict__ Kh, const uint32_t* __restrict__ Kl,
    const float* __restrict__ V,
    uint32_t* __restrict__ CtxH, uint32_t* __restrict__ CtxL)
{
    extern __shared__ uint32_t smw[];
    uint32_t* Ksh = smw;                    // 64*132
    uint32_t* Ksl = Ksh + QT * KW;
    uint32_t* VtH = Ksl + QT * KW;          // 64*36
    uint32_t* VtL = VtH + 64 * VTW;

    const int tid  = threadIdx.x;
    const int lane = tid & 31, warp = tid >> 5;       // warp 0..3
    const int g = lane >> 2, tig = lane & 3;
    const int bh = blockIdx.y, b = bh >> 4, h = bh & 15;
    const int s0 = blockIdx.x * QT;
    const float scale = 0.0625f;   // 1/sqrt(256)

    const int arow = ((lane >> 3) & 1) * 8 + (lane & 7);
    const int acol = (lane >> 4) * 4;
    const int brow = (lane >> 4) * 8 + (lane & 7);
    const int bcol = ((lane >> 3) & 1) * 4;

    // ---- stage Q tile into K buffers, then load A-frags to registers ----
    for (int idx = tid; idx < QT * 32; idx += 128) {
        int r = idx >> 5, w4 = (idx & 31) << 2;
        size_t gb = ((size_t)bh * SEQ + s0 + r) * (NF / 2) + w4;
        *(uint4*)&Ksh[r * KW + w4] = *(const uint4*)&Qh[gb];
        *(uint4*)&Ksl[r * KW + w4] = *(const uint4*)&Ql[gb];
    }
    __syncthreads();
    uint32_t qfh[16][4], qfl[16][4];
    {
        uint32_t baseH = s2u(Ksh) + ((warp * 16 + arow) * KW + acol) * 4;
        uint32_t baseL = s2u(Ksl) + ((warp * 16 + arow) * KW + acol) * 4;
        #pragma unroll
        for (int ks = 0; ks < 16; ks++) {
            ldsm4(qfh[ks][0], qfh[ks][1], qfh[ks][2], qfh[ks][3], baseH + ks * 32);
            ldsm4(qfl[ks][0], qfl[ks][1], qfl[ks][2], qfl[ks][3], baseL + ks * 32);
        }
    }

    const uint32_t kBh = s2u(Ksh) + (brow * KW + bcol) * 4;
    const uint32_t kBl = s2u(Ksl) + (brow * KW + bcol) * 4;
    const uint32_t vBh = s2u(VtH) + (brow * VTW + bcol) * 4;
    const uint32_t vBl = s2u(VtL) + (brow * VTW + bcol) * 4;

    float o[8][4] = {};
    float m0 = -1e30f, m1 = -1e30f, l0 = 0.f, l1 = 0.f;

    for (int t0 = 0; t0 < SEQ; t0 += TT) {
        __syncthreads();
        for (int idx = tid; idx < TT * 32; idx += 128) {
            int r = idx >> 5, w4 = (idx & 31) << 2;
            size_t gb = ((size_t)bh * SEQ + t0 + r) * (NF / 2) + w4;
            *(uint4*)&Ksh[r * KW + w4] = *(const uint4*)&Kh[gb];
            *(uint4*)&Ksl[r * KW + w4] = *(const uint4*)&Kl[gb];
        }
        for (int idx = tid; idx < TT * 16; idx += 128) {
            int t = idx >> 4, d4 = (idx & 15) << 2;
            float4 v = *(const float4*)&V[((size_t)b * SEQ + t0 + t) * DMODEL + h * HD + d4];
            float4 p;
            p.x = __shfl_xor_sync(0xffffffffu, v.x, 16);
            p.y = __shfl_xor_sync(0xffffffffu, v.y, 16);
            p.z = __shfl_xor_sync(0xffffffffu, v.z, 16);
            p.w = __shfl_xor_sync(0xffffffffu, v.w, 16);
            float ve[4], vo[4];
            if (t & 1) {
                ve[0]=p.x; ve[1]=p.y; ve[2]=p.z; ve[3]=p.w;
                vo[0]=v.x; vo[1]=v.y; vo[2]=v.z; vo[3]=v.w;
            } else {
                ve[0]=v.x; ve[1]=v.y; ve[2]=v.z; ve[3]=v.w;
                vo[0]=p.x; vo[1]=p.y; vo[2]=p.z; vo[3]=p.w;
            }
            int i0 = (t & 1) ? 2 : 0;
            int tw = t >> 1;
            #pragma unroll
            for (int i = 0; i < 2; i++) {
                uint32_t hw, lw;
                split_pack(ve[i0 + i], vo[i0 + i], hw, lw);
                VtH[(d4 + i0 + i) * VTW + tw] = hw;
                VtL[(d4 + i0 + i) * VTW + tw] = lw;
            }
        }
        __syncthreads();

        float c[8][4] = {};
        #pragma unroll
        for (int ks = 0; ks < 16; ks++) {
            uint32_t wbb = ks * 32;
            uint32_t bhf[8][2], blf[8][2];
            #pragma unroll
            for (int jj = 0; jj < 4; jj++) {
                uint32_t joff = jj * 16 * KW * 4 + wbb;
                ldsm4(bhf[jj*2][0], bhf[jj*2][1], bhf[jj*2+1][0], bhf[jj*2+1][1], kBh + joff);
                ldsm4(blf[jj*2][0], blf[jj*2][1], blf[jj*2+1][0], blf[jj*2+1][1], kBl + joff);
            }
            #pragma unroll
            for (int n = 0; n < 8; n++)
                mma3(c[n], qfh[ks], qfl[ks], bhf[n], blf[n]);
        }

        float mx0 = -1e30f, mx1 = -1e30f;
        #pragma unroll
        for (int n = 0; n < 8; n++) {
            mx0 = fmaxf(mx0, fmaxf(c[n][0], c[n][1]));
            mx1 = fmaxf(mx1, fmaxf(c[n][2], c[n][3]));
        }
        mx0 = fmaxf(mx0, __shfl_xor_sync(0xffffffffu, mx0, 1));
        mx0 = fmaxf(mx0, __shfl_xor_sync(0xffffffffu, mx0, 2));
        mx1 = fmaxf(mx1, __shfl_xor_sync(0xffffffffu, mx1, 1));
        mx1 = fmaxf(mx1, __shfl_xor_sync(0xffffffffu, mx1, 2));
        float mn0 = fmaxf(m0, mx0 * scale), mn1 = fmaxf(m1, mx1 * scale);
        float a0 = __expf(m0 - mn0), a1 = __expf(m1 - mn1);
        float sum0 = 0.f, sum1 = 0.f;
        #pragma unroll
        for (int n = 0; n < 8; n++) {
            c[n][0] = __expf(fmaf(c[n][0], scale, -mn0));
            c[n][1] = __expf(fmaf(c[n][1], scale, -mn0));
            c[n][2] = __expf(fmaf(c[n][2], scale, -mn1));
            c[n][3] = __expf(fmaf(c[n][3], scale, -mn1));
            sum0 += c[n][0] + c[n][1];
            sum1 += c[n][2] + c[n][3];
        }
        sum0 += __shfl_xor_sync(0xffffffffu, sum0, 1);
        sum0 += __shfl_xor_sync(0xffffffffu, sum0, 2);
        sum1 += __shfl_xor_sync(0xffffffffu, sum1, 1);
        sum1 += __shfl_xor_sync(0xffffffffu, sum1, 2);
        l0 = l0 * a0 + sum0; m0 = mn0;
        l1 = l1 * a1 + sum1; m1 = mn1;

        uint32_t pfh[4][4], pfl[4][4];
        #pragma unroll
        for (int k2 = 0; k2 < 4; k2++) {
            split_pack(c[2*k2  ][0], c[2*k2  ][1], pfh[k2][0], pfl[k2][0]);
            split_pack(c[2*k2  ][2], c[2*k2  ][3], pfh[k2][1], pfl[k2][1]);
            split_pack(c[2*k2+1][0], c[2*k2+1][1], pfh[k2][2], pfl[k2][2]);
            split_pack(c[2*k2+1][2], c[2*k2+1][3], pfh[k2][3], pfl[k2][3]);
        }

        #pragma unroll
        for (int n = 0; n < 8; n++) {
            o[n][0] *= a0; o[n][1] *= a0;
            o[n][2] *= a1; o[n][3] *= a1;
        }
        #pragma unroll
        for (int k2 = 0; k2 < 4; k2++) {
            uint32_t wbb = k2 * 32;
            uint32_t bhf[8][2], blf[8][2];
            #pragma unroll
            for (int jj = 0; jj < 4; jj++) {
                uint32_t joff = jj * 16 * VTW * 4 + wbb;
                ldsm4(bhf[jj*2][0], bhf[jj*2][1], bhf[jj*2+1][0], bhf[jj*2+1][1], vBh + joff);
                ldsm4(blf[jj*2][0], blf[jj*2][1], blf[jj*2+1][0], blf[jj*2+1][1], vBl + joff);
            }
            #pragma unroll
            for (int n = 0; n < 8; n++)
                mma3(o[n], pfh[k2], pfl[k2], bhf[n], blf[n]);
        }
    }

    // ---- epilogue: write ctx pre-split (packed bf16 hi/lo) ----
    float inv0 = 1.0f / l0, inv1 = 1.0f / l1;
    int r0 = s0 + warp * 16 + g;
    #pragma unroll
    for (int n = 0; n < 8; n++) {
        int dc = n * 8 + 2 * tig;
        size_t w0 = (((size_t)b * SEQ + r0) * DMODEL + h * HD + dc) >> 1;
        size_t w1 = (((size_t)b * SEQ + r0 + 8) * DMODEL + h * HD + dc) >> 1;
        split_pack(o[n][0] * inv0, o[n][1] * inv0, CtxH[w0], CtxL[w0]);
        split_pack(o[n][2] * inv1, o[n][3] * inv1, CtxH[w1], CtxL[w1]);
    }
}

// ---------------- launch ------------------------------------------------------
extern "C" void kernel_launch(void* const* d_in, const int* in_sizes, int n_in,
                              void* d_out, int out_size)
{
    (void)in_sizes; (void)n_in; (void)out_size;
    const float* x  = (const float*)d_in[0];
    const float* Wq = (const float*)d_in[1];
    const float* bq = (const float*)d_in[2];
    const float* Wk = (const float*)d_in[3];
    const float* bk = (const float*)d_in[4];
    const float* Wv = (const float*)d_in[5];
    const float* bv = (const float*)d_in[6];
    const float* Wo = (const float*)d_in[7];
    const float* bo = (const float*)d_in[8];
    const float* P  = (const float*)d_in[9];

    float *q, *k, *v;
    uint32_t *xh, *xl, *wh, *wl, *ctxh, *ctxl, *qph, *qpl, *kph, *kpl;
    cudaGetSymbolAddress((void**)&q,    g_q);
    cudaGetSymbolAddress((void**)&k,    g_k);
    cudaGetSymbolAddress((void**)&v,    g_v);
    cudaGetSymbolAddress((void**)&xh,   g_xh);
    cudaGetSymbolAddress((void**)&xl,   g_xl);
    cudaGetSymbolAddress((void**)&wh,   g_wh);
    cudaGetSymbolAddress((void**)&wl,   g_wl);
    cudaGetSymbolAddress((void**)&ctxh, g_ctxh);
    cudaGetSymbolAddress((void**)&ctxl, g_ctxl);
    cudaGetSymbolAddress((void**)&qph,  g_qph);
    cudaGetSymbolAddress((void**)&qpl,  g_qpl);
    cudaGetSymbolAddress((void**)&kph,  g_kph);
    cudaGetSymbolAddress((void**)&kpl,  g_kpl);

    const int WW = DMODEL * (DMODEL / 2);   // words per weight matrix
    split_f32<<<(MROWS * (DMODEL / 2)) / 1024, 256>>>(x, xh, xl, MROWS * (DMODEL / 2));
    split_f32<<<WW / 1024, 256>>>(Wq, wh + 0ull * WW, wl + 0ull * WW, WW);
    split_f32<<<WW / 1024, 256>>>(Wk, wh + 1ull * WW, wl + 1ull * WW, WW);
    split_f32<<<WW / 1024, 256>>>(Wv, wh + 2ull * WW, wl + 2ull * WW, WW);
    split_f32<<<WW / 1024, 256>>>(Wo, wh + 3ull * WW, wl + 3ull * WW, WW);

    const int GEMM_SMEM = 2 * GSOFF * 4;   // 61440 B
    cudaFuncSetAttribute(gemm_bf3p, cudaFuncAttributeMaxDynamicSharedMemorySize, GEMM_SMEM);
    dim3 gemm_grid(DMODEL / 64, MROWS / 128);   // (16, 64)
    gemm_bf3p<<<gemm_grid, 256, GEMM_SMEM>>>(xh, xl, wh + 0ull * WW, wl + 0ull * WW, bq, q, DMODEL, DMODEL);
    gemm_bf3p<<<gemm_grid, 256, GEMM_SMEM>>>(xh, xl, wh + 1ull * WW, wl + 1ull * WW, bk, k, DMODEL, DMODEL);
    gemm_bf3p<<<gemm_grid, 256, GEMM_SMEM>>>(xh, xl, wh + 2ull * WW, wl + 2ull * WW, bv, v, DMODEL, DMODEL);

    const int FP_SMEM = 4 * 128 * FPITCH * 4;    // 73728 B
    cudaFuncSetAttribute(featproj_mma, cudaFuncAttributeMaxDynamicSharedMemorySize, FP_SMEM);
    dim3 fp_grid(NF / 128, MROWS / 128, NHEADS); // (2, 64, 16)
    featproj_mma<<<fp_grid, 256, FP_SMEM>>>(q, P, qph, qpl);
    featproj_mma<<<fp_grid, 256, FP_SMEM>>>(k, P, kph, kpl);

    const int ATT_SMEM = (QT * KW * 2 + 64 * VTW * 2) * 4;   // 86016 B -> 2 CTA/SM
    cudaFuncSetAttribute(attn_bf3, cudaFuncAttributeMaxDynamicSharedMemorySize, ATT_SMEM);
    attn_bf3<<<dim3(SEQ / QT, BH), 128, ATT_SMEM>>>(qph, qpl, kph, kpl, v, ctxh, ctxl);

    gemm_bf3p<<<gemm_grid, 256, GEMM_SMEM>>>(ctxh, ctxl, wh + 3ull * WW, wl + 3ull * WW, bo,
                                             (float*)d_out, DMODEL, DMODEL);
}